// round 1
// baseline (speedup 1.0000x reference)
#include <cuda_runtime.h>
#include <math.h>
#include <stdint.h>

#define S_TOK 8192
#define H_DIM 1024
#define N_EXP 64
#define K_TOP 2
#define CAP 512
#define D_FF 2048
#define NROWS (N_EXP * CAP)  // 32768

// ---------------- scratch (device globals: no allocations allowed) ----------
__device__ float g_xn[(size_t)S_TOK * H_DIM];           // 32 MB
__device__ float g_h[(size_t)NROWS * D_FF];             // 256 MB
__device__ float g_od[(size_t)NROWS * H_DIM];           // 128 MB
__device__ int   g_row_tok[NROWS];
__device__ int   g_count[N_EXP];
__device__ int   g_pair_idx[S_TOK * K_TOP];
__device__ float g_pair_w[S_TOK * K_TOP];

// ---------------- f32x2 helpers (Blackwell packed fp32) ---------------------
__device__ __forceinline__ unsigned long long fma2(unsigned long long a,
                                                   unsigned long long b,
                                                   unsigned long long c) {
    unsigned long long d;
    asm("fma.rn.f32x2 %0, %1, %2, %3;" : "=l"(d) : "l"(a), "l"(b), "l"(c));
    return d;
}
__device__ __forceinline__ float2 unpack2(unsigned long long v) {
    float2 r;
    asm("mov.b64 {%0, %1}, %2;" : "=f"(r.x), "=f"(r.y) : "l"(v));
    return r;
}
__device__ __forceinline__ unsigned long long dup2(float x) {
    unsigned long long v;
    asm("mov.b64 %0, {%1, %1};" : "=l"(v) : "f"(x));
    return v;
}
__device__ __forceinline__ float silu_f(float v) {
    return v / (1.0f + expf(-v));
}

// ---------------- 0: zero expert counters ----------------------------------
__global__ void k_zero_counts() {
    if (threadIdx.x < N_EXP) g_count[threadIdx.x] = 0;
}

// ---------------- 1: RMSNorm -------------------------------------------------
__global__ void k_rmsnorm(const float* __restrict__ x,
                          const float* __restrict__ w) {
    int tok = blockIdx.x;
    int t = threadIdx.x;  // 256 threads, float4 each -> 1024
    float4 v = ((const float4*)(x + (size_t)tok * H_DIM))[t];
    float ss = v.x * v.x + v.y * v.y + v.z * v.z + v.w * v.w;
#pragma unroll
    for (int o = 16; o > 0; o >>= 1) ss += __shfl_xor_sync(0xffffffffu, ss, o);
    __shared__ float red[8];
    if ((t & 31) == 0) red[t >> 5] = ss;
    __syncthreads();
    float tot = red[0] + red[1] + red[2] + red[3] + red[4] + red[5] + red[6] + red[7];
    float scale = rsqrtf(tot * (1.0f / H_DIM) + 1e-6f);
    float4 wv = ((const float4*)w)[t];
    float4 o;
    o.x = v.x * scale * wv.x;
    o.y = v.y * scale * wv.y;
    o.z = v.z * scale * wv.z;
    o.w = v.w * scale * wv.w;
    ((float4*)(g_xn + (size_t)tok * H_DIM))[t] = o;
}

// ---------------- 2: router GEMM (64 tok x 64 exp) + top2 + slot assign -----
__global__ void k_router(const float* __restrict__ rw) {
    __shared__ float As[16][64];
    __shared__ float Bs[16][64];
    __shared__ float Ss[64][65];
    int t = threadIdx.x;  // 256
    int tok0 = blockIdx.x * 64;
    int ty = t >> 4, tx = t & 15;
    float acc[4][4];
#pragma unroll
    for (int i = 0; i < 4; i++)
#pragma unroll
        for (int j = 0; j < 4; j++) acc[i][j] = 0.0f;

    int lr = t >> 2;        // 0..63
    int lk = (t & 3) * 4;   // 0,4,8,12
    const float* ap = g_xn + (size_t)(tok0 + lr) * H_DIM + lk;
    const float* bp = rw + (size_t)lr * H_DIM + lk;

    for (int k0 = 0; k0 < H_DIM; k0 += 16) {
        float4 av = *(const float4*)(ap + k0);
        float4 bv = *(const float4*)(bp + k0);
        __syncthreads();
        As[lk + 0][lr] = av.x; As[lk + 1][lr] = av.y;
        As[lk + 2][lr] = av.z; As[lk + 3][lr] = av.w;
        Bs[lk + 0][lr] = bv.x; Bs[lk + 1][lr] = bv.y;
        Bs[lk + 2][lr] = bv.z; Bs[lk + 3][lr] = bv.w;
        __syncthreads();
#pragma unroll
        for (int kk = 0; kk < 16; kk++) {
            float a[4], b[4];
#pragma unroll
            for (int i = 0; i < 4; i++) a[i] = As[kk][ty * 4 + i];
#pragma unroll
            for (int j = 0; j < 4; j++) b[j] = Bs[kk][tx * 4 + j];
#pragma unroll
            for (int i = 0; i < 4; i++)
#pragma unroll
                for (int j = 0; j < 4; j++) acc[i][j] = fmaf(a[i], b[j], acc[i][j]);
        }
    }
    __syncthreads();
#pragma unroll
    for (int i = 0; i < 4; i++)
#pragma unroll
        for (int j = 0; j < 4; j++) Ss[ty * 4 + i][tx * 4 + j] = acc[i][j];
    __syncthreads();

    if (t < 64) {
        int tok = tok0 + t;
        float v1 = -1e30f, v2 = -1e30f;
        int i1 = 0, i2 = 0;
#pragma unroll 4
        for (int e = 0; e < N_EXP; e++) {
            float s = Ss[t][e];
            if (s > v1) { v2 = v1; i2 = i1; v1 = s; i1 = e; }
            else if (s > v2) { v2 = s; i2 = e; }
        }
        float ex = expf(v2 - v1);
        float wB = ex / (1.0f + ex);
        float wA = 1.0f - wB;

        int s1 = atomicAdd(&g_count[i1], 1);
        if (s1 < CAP) {
            g_row_tok[i1 * CAP + s1] = tok;
            g_pair_idx[tok * 2] = i1 * CAP + s1;
            g_pair_w[tok * 2] = wA;
        } else {
            g_pair_idx[tok * 2] = -1;
        }
        int s2 = atomicAdd(&g_count[i2], 1);
        if (s2 < CAP) {
            g_row_tok[i2 * CAP + s2] = tok;
            g_pair_idx[tok * 2 + 1] = i2 * CAP + s2;
            g_pair_w[tok * 2 + 1] = wB;
        } else {
            g_pair_idx[tok * 2 + 1] = -1;
        }
    }
}

// ---------------- 3: GEMM1  h = silu(xn[gather] @ w1[e]^T) ------------------
// BM=128 (slots), BN=128 (d_ff), BK=8, 256 threads, 8x8 micro-tile via f32x2.
__global__ void __launch_bounds__(256, 2) k_gemm1(const float* __restrict__ w1) {
    int e = blockIdx.z;
    int cnt = min(g_count[e], CAP);
    int m0 = blockIdx.y * 128;
    if (m0 >= cnt) return;
    int n0 = blockIdx.x * 128;

    __shared__ float As[8][128];
    __shared__ unsigned long long Bs[8][128];  // B duplicated into both halves
    __shared__ int stok[128];

    int t = threadIdx.x;
    if (t < 128) {
        int slot = m0 + t;
        stok[t] = (slot < cnt) ? g_row_tok[e * CAP + slot] : -1;
    }
    __syncthreads();

    int lr = t >> 1;        // 0..127
    int lk = (t & 1) * 4;   // 0 or 4
    int atok = stok[lr];
    const float* aptr = (atok >= 0) ? (g_xn + (size_t)atok * H_DIM + lk) : 0;
    const float* bptr = w1 + ((size_t)e * D_FF + n0 + lr) * H_DIM + lk;

    int ty = t >> 4, tx = t & 15;
    unsigned long long acc[4][8];
#pragma unroll
    for (int i = 0; i < 4; i++)
#pragma unroll
        for (int j = 0; j < 8; j++) acc[i][j] = 0ull;

    for (int k0 = 0; k0 < H_DIM; k0 += 8) {
        float4 av = aptr ? *(const float4*)(aptr + k0) : make_float4(0.f, 0.f, 0.f, 0.f);
        float4 bv = *(const float4*)(bptr + k0);
        __syncthreads();
        As[lk + 0][lr] = av.x; As[lk + 1][lr] = av.y;
        As[lk + 2][lr] = av.z; As[lk + 3][lr] = av.w;
        Bs[lk + 0][lr] = dup2(bv.x); Bs[lk + 1][lr] = dup2(bv.y);
        Bs[lk + 2][lr] = dup2(bv.z); Bs[lk + 3][lr] = dup2(bv.w);
        __syncthreads();
#pragma unroll
        for (int kk = 0; kk < 8; kk++) {
            ulonglong2 a01 = *(const ulonglong2*)&As[kk][ty * 8];
            ulonglong2 a23 = *(const ulonglong2*)&As[kk][ty * 8 + 4];
            unsigned long long am[4] = {a01.x, a01.y, a23.x, a23.y};
            ulonglong2 b01 = *(const ulonglong2*)&Bs[kk][tx * 8];
            ulonglong2 b23 = *(const ulonglong2*)&Bs[kk][tx * 8 + 2];
            ulonglong2 b45 = *(const ulonglong2*)&Bs[kk][tx * 8 + 4];
            ulonglong2 b67 = *(const ulonglong2*)&Bs[kk][tx * 8 + 6];
            unsigned long long bm[8] = {b01.x, b01.y, b23.x, b23.y,
                                        b45.x, b45.y, b67.x, b67.y};
#pragma unroll
            for (int i = 0; i < 4; i++)
#pragma unroll
                for (int j = 0; j < 8; j++) acc[i][j] = fma2(am[i], bm[j], acc[i][j]);
        }
    }

    int col = n0 + tx * 8;
    size_t rowbase = (size_t)(e * CAP + m0 + ty * 8);
#pragma unroll
    for (int i2 = 0; i2 < 4; i2++) {
        float lo[8], hi[8];
#pragma unroll
        for (int j = 0; j < 8; j++) {
            float2 p = unpack2(acc[i2][j]);
            lo[j] = p.x; hi[j] = p.y;
        }
        size_t r0 = rowbase + i2 * 2;
        float4 o;
        o.x = silu_f(lo[0]); o.y = silu_f(lo[1]); o.z = silu_f(lo[2]); o.w = silu_f(lo[3]);
        *(float4*)(g_h + r0 * D_FF + col) = o;
        o.x = silu_f(lo[4]); o.y = silu_f(lo[5]); o.z = silu_f(lo[6]); o.w = silu_f(lo[7]);
        *(float4*)(g_h + r0 * D_FF + col + 4) = o;
        o.x = silu_f(hi[0]); o.y = silu_f(hi[1]); o.z = silu_f(hi[2]); o.w = silu_f(hi[3]);
        *(float4*)(g_h + (r0 + 1) * D_FF + col) = o;
        o.x = silu_f(hi[4]); o.y = silu_f(hi[5]); o.z = silu_f(hi[6]); o.w = silu_f(hi[7]);
        *(float4*)(g_h + (r0 + 1) * D_FF + col + 4) = o;
    }
}

// ---------------- 4: GEMM2  od = h @ w2[e]^T ---------------------------------
__global__ void __launch_bounds__(256, 2) k_gemm2(const float* __restrict__ w2) {
    int e = blockIdx.z;
    int cnt = min(g_count[e], CAP);
    int m0 = blockIdx.y * 128;
    if (m0 >= cnt) return;
    int n0 = blockIdx.x * 128;

    __shared__ float As[8][128];
    __shared__ unsigned long long Bs[8][128];

    int t = threadIdx.x;
    int lr = t >> 1;
    int lk = (t & 1) * 4;
    const float* aptr = g_h + (size_t)(e * CAP + m0 + lr) * D_FF + lk;
    const float* bptr = w2 + ((size_t)e * H_DIM + n0 + lr) * D_FF + lk;

    int ty = t >> 4, tx = t & 15;
    unsigned long long acc[4][8];
#pragma unroll
    for (int i = 0; i < 4; i++)
#pragma unroll
        for (int j = 0; j < 8; j++) acc[i][j] = 0ull;

    for (int k0 = 0; k0 < D_FF; k0 += 8) {
        float4 av = *(const float4*)(aptr + k0);
        float4 bv = *(const float4*)(bptr + k0);
        __syncthreads();
        As[lk + 0][lr] = av.x; As[lk + 1][lr] = av.y;
        As[lk + 2][lr] = av.z; As[lk + 3][lr] = av.w;
        Bs[lk + 0][lr] = dup2(bv.x); Bs[lk + 1][lr] = dup2(bv.y);
        Bs[lk + 2][lr] = dup2(bv.z); Bs[lk + 3][lr] = dup2(bv.w);
        __syncthreads();
#pragma unroll
        for (int kk = 0; kk < 8; kk++) {
            ulonglong2 a01 = *(const ulonglong2*)&As[kk][ty * 8];
            ulonglong2 a23 = *(const ulonglong2*)&As[kk][ty * 8 + 4];
            unsigned long long am[4] = {a01.x, a01.y, a23.x, a23.y};
            ulonglong2 b01 = *(const ulonglong2*)&Bs[kk][tx * 8];
            ulonglong2 b23 = *(const ulonglong2*)&Bs[kk][tx * 8 + 2];
            ulonglong2 b45 = *(const ulonglong2*)&Bs[kk][tx * 8 + 4];
            ulonglong2 b67 = *(const ulonglong2*)&Bs[kk][tx * 8 + 6];
            unsigned long long bm[8] = {b01.x, b01.y, b23.x, b23.y,
                                        b45.x, b45.y, b67.x, b67.y};
#pragma unroll
            for (int i = 0; i < 4; i++)
#pragma unroll
                for (int j = 0; j < 8; j++) acc[i][j] = fma2(am[i], bm[j], acc[i][j]);
        }
    }

    int col = n0 + tx * 8;
    size_t rowbase = (size_t)(e * CAP + m0 + ty * 8);
#pragma unroll
    for (int i2 = 0; i2 < 4; i2++) {
        float lo[8], hi[8];
#pragma unroll
        for (int j = 0; j < 8; j++) {
            float2 p = unpack2(acc[i2][j]);
            lo[j] = p.x; hi[j] = p.y;
        }
        size_t r0 = rowbase + i2 * 2;
        *(float4*)(g_od + r0 * H_DIM + col)           = make_float4(lo[0], lo[1], lo[2], lo[3]);
        *(float4*)(g_od + r0 * H_DIM + col + 4)       = make_float4(lo[4], lo[5], lo[6], lo[7]);
        *(float4*)(g_od + (r0 + 1) * H_DIM + col)     = make_float4(hi[0], hi[1], hi[2], hi[3]);
        *(float4*)(g_od + (r0 + 1) * H_DIM + col + 4) = make_float4(hi[4], hi[5], hi[6], hi[7]);
    }
}

// ---------------- 5: combine  out = x + w0*od[p0] + w1*od[p1] ---------------
__global__ void k_combine(const float* __restrict__ x, float* __restrict__ out) {
    int tok = blockIdx.x;
    int t = threadIdx.x;  // 256, float4 each
    int p0 = g_pair_idx[tok * 2];
    int p1 = g_pair_idx[tok * 2 + 1];
    float w0 = g_pair_w[tok * 2];
    float w1 = g_pair_w[tok * 2 + 1];
    float4 v = ((const float4*)(x + (size_t)tok * H_DIM))[t];
    if (p0 >= 0) {
        float4 o = ((const float4*)(g_od + (size_t)p0 * H_DIM))[t];
        v.x += w0 * o.x; v.y += w0 * o.y; v.z += w0 * o.z; v.w += w0 * o.w;
    }
    if (p1 >= 0) {
        float4 o = ((const float4*)(g_od + (size_t)p1 * H_DIM))[t];
        v.x += w1 * o.x; v.y += w1 * o.y; v.z += w1 * o.z; v.w += w1 * o.w;
    }
    ((float4*)(out + (size_t)tok * H_DIM))[t] = v;
}

// ---------------- launch ------------------------------------------------------
extern "C" void kernel_launch(void* const* d_in, const int* in_sizes, int n_in,
                              void* d_out, int out_size) {
    const float* x        = (const float*)d_in[0];
    const float* rms_w    = (const float*)d_in[1];
    const float* router_w = (const float*)d_in[2];
    const float* w1       = (const float*)d_in[3];
    const float* w2       = (const float*)d_in[4];
    float* out = (float*)d_out;

    k_zero_counts<<<1, 64>>>();
    k_rmsnorm<<<S_TOK, 256>>>(x, rms_w);
    k_router<<<S_TOK / 64, 256>>>(router_w);
    k_gemm1<<<dim3(D_FF / 128, CAP / 128, N_EXP), 256>>>(w1);
    k_gemm2<<<dim3(H_DIM / 128, CAP / 128, N_EXP), 256>>>(w2);
    k_combine<<<S_TOK, 256>>>(x, out);
}

// round 3
// speedup vs baseline: 3.8495x; 3.8495x over previous
#include <cuda_runtime.h>
#include <cuda_bf16.h>
#include <math.h>
#include <stdint.h>

#define S_TOK 8192
#define H_DIM 1024
#define N_EXP 64
#define CAP 512
#define D_FF 2048
#define NROWS (N_EXP * CAP)  // 32768

// ---------------- scratch (device globals) ----------------------------------
__device__ float g_xn[(size_t)S_TOK * H_DIM];                 // 32 MB
__device__ __nv_bfloat16 g_h_hi[(size_t)NROWS * D_FF];        // 128 MB
__device__ __nv_bfloat16 g_h_lo[(size_t)NROWS * D_FF];        // 128 MB
__device__ float g_od[(size_t)NROWS * H_DIM];                 // 128 MB
__device__ int   g_row_tok[NROWS];
__device__ int   g_count[N_EXP];
__device__ int   g_pair_idx[S_TOK * 2];
__device__ float g_pair_w[S_TOK * 2];

// ---------------- helpers -----------------------------------------------------
__device__ __forceinline__ uint32_t smem_u32(const void* p) {
    uint32_t a;
    asm("{ .reg .u64 t; cvta.to.shared.u64 t, %1; cvt.u32.u64 %0, t; }"
        : "=r"(a) : "l"(p));
    return a;
}
__device__ __forceinline__ void ldsm4(uint32_t* r, uint32_t addr) {
    asm volatile("ldmatrix.sync.aligned.m8n8.x4.shared.b16 {%0,%1,%2,%3}, [%4];"
                 : "=r"(r[0]), "=r"(r[1]), "=r"(r[2]), "=r"(r[3]) : "r"(addr));
}
__device__ __forceinline__ void mma_bf16(float* d, const uint32_t* a,
                                         uint32_t b0, uint32_t b1) {
    asm volatile("mma.sync.aligned.m16n8k16.row.col.f32.bf16.bf16.f32 "
                 "{%0,%1,%2,%3}, {%4,%5,%6,%7}, {%8,%9}, {%0,%1,%2,%3};"
                 : "+f"(d[0]), "+f"(d[1]), "+f"(d[2]), "+f"(d[3])
                 : "r"(a[0]), "r"(a[1]), "r"(a[2]), "r"(a[3]), "r"(b0), "r"(b1));
}
__device__ __forceinline__ uint32_t pack_bf2(float a, float b) {
    __nv_bfloat162 t = __floats2bfloat162_rn(a, b);
    return *reinterpret_cast<uint32_t*>(&t);
}
// convert float4 -> 4 bf16 hi (8B) + 4 bf16 lo (8B), store at byte offset off
__device__ __forceinline__ void cvt_store(char* hib, char* lob, uint32_t off, float4 v) {
    float hx = __bfloat162float(__float2bfloat16(v.x));
    float hy = __bfloat162float(__float2bfloat16(v.y));
    float hz = __bfloat162float(__float2bfloat16(v.z));
    float hw = __bfloat162float(__float2bfloat16(v.w));
    uint2 H, L;
    H.x = pack_bf2(hx, hy);       H.y = pack_bf2(hz, hw);
    L.x = pack_bf2(v.x - hx, v.y - hy);
    L.y = pack_bf2(v.z - hz, v.w - hw);
    *reinterpret_cast<uint2*>(hib + off) = H;
    *reinterpret_cast<uint2*>(lob + off) = L;
}
__device__ __forceinline__ float silu_f(float v) { return v / (1.0f + expf(-v)); }

// smem geometry: rows padded to 72 bf16 = 144B (conflict-free LDSM + STS)
#define ROWB 144
#define A_H 0
#define A_L 18432
#define B_H 36864
#define B_L 55296
#define BUF 73728
#define SMEM_SZ (2 * BUF)  // 147456

// ---------------- 0: zero expert counters ------------------------------------
__global__ void k_zero_counts() {
    if (threadIdx.x < N_EXP) g_count[threadIdx.x] = 0;
}

// ---------------- 1: RMSNorm --------------------------------------------------
__global__ void k_rmsnorm(const float* __restrict__ x, const float* __restrict__ w) {
    int tok = blockIdx.x;
    int t = threadIdx.x;
    float4 v = ((const float4*)(x + (size_t)tok * H_DIM))[t];
    float ss = v.x * v.x + v.y * v.y + v.z * v.z + v.w * v.w;
#pragma unroll
    for (int o = 16; o > 0; o >>= 1) ss += __shfl_xor_sync(0xffffffffu, ss, o);
    __shared__ float red[8];
    if ((t & 31) == 0) red[t >> 5] = ss;
    __syncthreads();
    float tot = red[0] + red[1] + red[2] + red[3] + red[4] + red[5] + red[6] + red[7];
    float scale = rsqrtf(tot * (1.0f / H_DIM) + 1e-6f);
    float4 wv = ((const float4*)w)[t];
    float4 o;
    o.x = v.x * scale * wv.x; o.y = v.y * scale * wv.y;
    o.z = v.z * scale * wv.z; o.w = v.w * scale * wv.w;
    ((float4*)(g_xn + (size_t)tok * H_DIM))[t] = o;
}

// ---------------- 2: router + top2 + slot assign ------------------------------
__global__ void k_router(const float* __restrict__ rw) {
    __shared__ float As[16][64];
    __shared__ float Bs[16][64];
    __shared__ float Ss[64][65];
    int t = threadIdx.x;
    int tok0 = blockIdx.x * 64;
    int ty = t >> 4, tx = t & 15;
    float acc[4][4];
#pragma unroll
    for (int i = 0; i < 4; i++)
#pragma unroll
        for (int j = 0; j < 4; j++) acc[i][j] = 0.0f;

    int lr = t >> 2;
    int lk = (t & 3) * 4;
    const float* ap = g_xn + (size_t)(tok0 + lr) * H_DIM + lk;
    const float* bp = rw + (size_t)lr * H_DIM + lk;

    for (int k0 = 0; k0 < H_DIM; k0 += 16) {
        float4 av = *(const float4*)(ap + k0);
        float4 bv = *(const float4*)(bp + k0);
        __syncthreads();
        As[lk + 0][lr] = av.x; As[lk + 1][lr] = av.y;
        As[lk + 2][lr] = av.z; As[lk + 3][lr] = av.w;
        Bs[lk + 0][lr] = bv.x; Bs[lk + 1][lr] = bv.y;
        Bs[lk + 2][lr] = bv.z; Bs[lk + 3][lr] = bv.w;
        __syncthreads();
#pragma unroll
        for (int kk = 0; kk < 16; kk++) {
            float a[4], b[4];
#pragma unroll
            for (int i = 0; i < 4; i++) a[i] = As[kk][ty * 4 + i];
#pragma unroll
            for (int j = 0; j < 4; j++) b[j] = Bs[kk][tx * 4 + j];
#pragma unroll
            for (int i = 0; i < 4; i++)
#pragma unroll
                for (int j = 0; j < 4; j++) acc[i][j] = fmaf(a[i], b[j], acc[i][j]);
        }
    }
    __syncthreads();
#pragma unroll
    for (int i = 0; i < 4; i++)
#pragma unroll
        for (int j = 0; j < 4; j++) Ss[ty * 4 + i][tx * 4 + j] = acc[i][j];
    __syncthreads();

    if (t < 64) {
        int tok = tok0 + t;
        float v1 = -1e30f, v2 = -1e30f;
        int i1 = 0, i2 = 0;
#pragma unroll 4
        for (int e = 0; e < N_EXP; e++) {
            float s = Ss[t][e];
            if (s > v1) { v2 = v1; i2 = i1; v1 = s; i1 = e; }
            else if (s > v2) { v2 = s; i2 = e; }
        }
        float ex = expf(v2 - v1);
        float wB = ex / (1.0f + ex);
        float wA = 1.0f - wB;

        int s1 = atomicAdd(&g_count[i1], 1);
        if (s1 < CAP) {
            g_row_tok[i1 * CAP + s1] = tok;
            g_pair_idx[tok * 2] = i1 * CAP + s1;
            g_pair_w[tok * 2] = wA;
        } else g_pair_idx[tok * 2] = -1;
        int s2 = atomicAdd(&g_count[i2], 1);
        if (s2 < CAP) {
            g_row_tok[i2 * CAP + s2] = tok;
            g_pair_idx[tok * 2 + 1] = i2 * CAP + s2;
            g_pair_w[tok * 2 + 1] = wB;
        } else g_pair_idx[tok * 2 + 1] = -1;
    }
}

// ---------------- GEMM1: h = silu(xn[gather] @ w1[e]^T), split to bf16 hi/lo --
// 128x128 CTA tile, BK=64 fp32, 512 threads (16 warps, 32x32 warp tiles).
__global__ void __launch_bounds__(512, 1) k_gemm1(const float* __restrict__ w1) {
    int e = blockIdx.z;
    int cnt = min(g_count[e], CAP);
    int m0 = blockIdx.y * 128;
    if (m0 >= cnt) return;
    int n0 = blockIdx.x * 128;

    extern __shared__ char sm[];
    __shared__ int stok[128];
    int t = threadIdx.x;
    int lane = t & 31, w = t >> 5;

    if (t < 128) {
        int s = m0 + t;
        stok[t] = (s < cnt) ? g_row_tok[e * CAP + s] : -1;
    }
    __syncthreads();

    int row = t >> 2;          // 0..127
    int ch = (t & 3) * 16;     // element col base within chunk
    int mytok = stok[row];
    const float* ap = (mytok >= 0) ? g_xn + (size_t)mytok * H_DIM + ch : nullptr;
    const float* bp = w1 + ((size_t)e * D_FF + n0 + row) * H_DIM + ch;
    uint32_t sts_off = row * ROWB + ch * 2;

    int wm = (w & 3) * 32;
    int wn = (w >> 2) * 32;
    uint32_t smb = smem_u32(sm);
    uint32_t lrow = lane & 15;
    uint32_t lcol = (lane >> 4) << 4;
    uint32_t lmA = (wm + lrow) * ROWB + lcol;
    uint32_t lmB = (wn + lrow) * ROWB + lcol;

    float acc[2][4][4];
#pragma unroll
    for (int mf = 0; mf < 2; mf++)
#pragma unroll
        for (int nf = 0; nf < 4; nf++)
#pragma unroll
            for (int k = 0; k < 4; k++) acc[mf][nf][k] = 0.0f;

    float4 pa[4], pb[4];
#pragma unroll
    for (int j = 0; j < 4; j++) {
        pa[j] = ap ? *(const float4*)(ap + j * 4) : make_float4(0.f, 0.f, 0.f, 0.f);
        pb[j] = *(const float4*)(bp + j * 4);
    }

    const int NC = H_DIM / 64;  // 16
#pragma unroll 1
    for (int c = 0; c < NC; c++) {
        char* buf = sm + (c & 1) * BUF;
#pragma unroll
        for (int j = 0; j < 4; j++) {
            cvt_store(buf + A_H, buf + A_L, sts_off + j * 8, pa[j]);
            cvt_store(buf + B_H, buf + B_L, sts_off + j * 8, pb[j]);
        }
        __syncthreads();
        if (c + 1 < NC) {
#pragma unroll
            for (int j = 0; j < 4; j++) {
                pa[j] = ap ? *(const float4*)(ap + (c + 1) * 64 + j * 4)
                           : make_float4(0.f, 0.f, 0.f, 0.f);
                pb[j] = *(const float4*)(bp + (c + 1) * 64 + j * 4);
            }
        }
        uint32_t bb = smb + (c & 1) * BUF;
#pragma unroll
        for (int kk = 0; kk < 4; kk++) {
            uint32_t ko = kk * 32;
            uint32_t ah[2][4], al[2][4], bh[2][4], bl[2][4];
            ldsm4(ah[0], bb + A_H + lmA + ko);
            ldsm4(ah[1], bb + A_H + lmA + 16 * ROWB + ko);
            ldsm4(al[0], bb + A_L + lmA + ko);
            ldsm4(al[1], bb + A_L + lmA + 16 * ROWB + ko);
            ldsm4(bh[0], bb + B_H + lmB + ko);
            ldsm4(bh[1], bb + B_H + lmB + 16 * ROWB + ko);
            ldsm4(bl[0], bb + B_L + lmB + ko);
            ldsm4(bl[1], bb + B_L + lmB + 16 * ROWB + ko);
#pragma unroll
            for (int mf = 0; mf < 2; mf++)
#pragma unroll
                for (int nf = 0; nf < 4; nf++) {
                    int g = nf >> 1, s = nf & 1;
                    mma_bf16(acc[mf][nf], ah[mf], bh[g][s], bh[g][s + 2]);
                    mma_bf16(acc[mf][nf], al[mf], bh[g][s], bh[g][s + 2]);
                    mma_bf16(acc[mf][nf], ah[mf], bl[g][s], bl[g][s + 2]);
                }
        }
    }

    // epilogue: silu, split hi/lo, store
    int r0 = m0 + wm + (lane >> 2);
    size_t ebase = (size_t)e * CAP;
#pragma unroll
    for (int mf = 0; mf < 2; mf++) {
#pragma unroll
        for (int nf = 0; nf < 4; nf++) {
            int col = n0 + wn + nf * 8 + (lane & 3) * 2;
#pragma unroll
            for (int half = 0; half < 2; half++) {
                size_t r = ebase + r0 + mf * 16 + half * 8;
                float s0 = silu_f(acc[mf][nf][half * 2]);
                float s1 = silu_f(acc[mf][nf][half * 2 + 1]);
                float h0 = __bfloat162float(__float2bfloat16(s0));
                float h1 = __bfloat162float(__float2bfloat16(s1));
                *(uint32_t*)(g_h_hi + r * D_FF + col) = pack_bf2(h0, h1);
                *(uint32_t*)(g_h_lo + r * D_FF + col) = pack_bf2(s0 - h0, s1 - h1);
            }
        }
    }
}

// ---------------- GEMM2: od = h @ w2[e]^T (A already split) -------------------
__global__ void __launch_bounds__(512, 1) k_gemm2(const float* __restrict__ w2) {
    int e = blockIdx.z;
    int cnt = min(g_count[e], CAP);
    int m0 = blockIdx.y * 128;
    if (m0 >= cnt) return;
    int n0 = blockIdx.x * 128;

    extern __shared__ char sm[];
    int t = threadIdx.x;
    int lane = t & 31, w = t >> 5;

    int row = t >> 2;
    int ch = (t & 3) * 16;
    size_t arow = ((size_t)e * CAP + m0 + row) * D_FF + ch;
    const float* bp = w2 + ((size_t)e * H_DIM + n0 + row) * D_FF + ch;
    uint32_t sts_off = row * ROWB + ch * 2;

    int wm = (w & 3) * 32;
    int wn = (w >> 2) * 32;
    uint32_t smb = smem_u32(sm);
    uint32_t lrow = lane & 15;
    uint32_t lcol = (lane >> 4) << 4;
    uint32_t lmA = (wm + lrow) * ROWB + lcol;
    uint32_t lmB = (wn + lrow) * ROWB + lcol;

    float acc[2][4][4];
#pragma unroll
    for (int mf = 0; mf < 2; mf++)
#pragma unroll
        for (int nf = 0; nf < 4; nf++)
#pragma unroll
            for (int k = 0; k < 4; k++) acc[mf][nf][k] = 0.0f;

    uint4 pah[2], pal[2];
    float4 pb[4];
#pragma unroll
    for (int j = 0; j < 2; j++) {
        pah[j] = *(const uint4*)(g_h_hi + arow + j * 8);
        pal[j] = *(const uint4*)(g_h_lo + arow + j * 8);
    }
#pragma unroll
    for (int j = 0; j < 4; j++) pb[j] = *(const float4*)(bp + j * 4);

    const int NC = D_FF / 64;  // 32
#pragma unroll 1
    for (int c = 0; c < NC; c++) {
        char* buf = sm + (c & 1) * BUF;
#pragma unroll
        for (int j = 0; j < 2; j++) {
            *(uint4*)(buf + A_H + sts_off + j * 16) = pah[j];
            *(uint4*)(buf + A_L + sts_off + j * 16) = pal[j];
        }
#pragma unroll
        for (int j = 0; j < 4; j++)
            cvt_store(buf + B_H, buf + B_L, sts_off + j * 8, pb[j]);
        __syncthreads();
        if (c + 1 < NC) {
#pragma unroll
            for (int j = 0; j < 2; j++) {
                pah[j] = *(const uint4*)(g_h_hi + arow + (c + 1) * 64 + j * 8);
                pal[j] = *(const uint4*)(g_h_lo + arow + (c + 1) * 64 + j * 8);
            }
#pragma unroll
            for (int j = 0; j < 4; j++)
                pb[j] = *(const float4*)(bp + (c + 1) * 64 + j * 4);
        }
        uint32_t bb = smb + (c & 1) * BUF;
#pragma unroll
        for (int kk = 0; kk < 4; kk++) {
            uint32_t ko = kk * 32;
            uint32_t ah[2][4], al[2][4], bh[2][4], bl[2][4];
            ldsm4(ah[0], bb + A_H + lmA + ko);
            ldsm4(ah[1], bb + A_H + lmA + 16 * ROWB + ko);
            ldsm4(al[0], bb + A_L + lmA + ko);
            ldsm4(al[1], bb + A_L + lmA + 16 * ROWB + ko);
            ldsm4(bh[0], bb + B_H + lmB + ko);
            ldsm4(bh[1], bb + B_H + lmB + 16 * ROWB + ko);
            ldsm4(bl[0], bb + B_L + lmB + ko);
            ldsm4(bl[1], bb + B_L + lmB + 16 * ROWB + ko);
#pragma unroll
            for (int mf = 0; mf < 2; mf++)
#pragma unroll
                for (int nf = 0; nf < 4; nf++) {
                    int g = nf >> 1, s = nf & 1;
                    mma_bf16(acc[mf][nf], ah[mf], bh[g][s], bh[g][s + 2]);
                    mma_bf16(acc[mf][nf], al[mf], bh[g][s], bh[g][s + 2]);
                    mma_bf16(acc[mf][nf], ah[mf], bl[g][s], bl[g][s + 2]);
                }
        }
    }

    int r0 = m0 + wm + (lane >> 2);
    size_t ebase = (size_t)e * CAP;
#pragma unroll
    for (int mf = 0; mf < 2; mf++) {
#pragma unroll
        for (int nf = 0; nf < 4; nf++) {
            int col = n0 + wn + nf * 8 + (lane & 3) * 2;
#pragma unroll
            for (int half = 0; half < 2; half++) {
                size_t r = ebase + r0 + mf * 16 + half * 8;
                *(float2*)(g_od + r * H_DIM + col) =
                    make_float2(acc[mf][nf][half * 2], acc[mf][nf][half * 2 + 1]);
            }
        }
    }
}

// ---------------- 5: combine ---------------------------------------------------
__global__ void k_combine(const float* __restrict__ x, float* __restrict__ out) {
    int tok = blockIdx.x;
    int t = threadIdx.x;
    int p0 = g_pair_idx[tok * 2];
    int p1 = g_pair_idx[tok * 2 + 1];
    float w0 = g_pair_w[tok * 2];
    float w1 = g_pair_w[tok * 2 + 1];
    float4 v = ((const float4*)(x + (size_t)tok * H_DIM))[t];
    if (p0 >= 0) {
        float4 o = ((const float4*)(g_od + (size_t)p0 * H_DIM))[t];
        v.x += w0 * o.x; v.y += w0 * o.y; v.z += w0 * o.z; v.w += w0 * o.w;
    }
    if (p1 >= 0) {
        float4 o = ((const float4*)(g_od + (size_t)p1 * H_DIM))[t];
        v.x += w1 * o.x; v.y += w1 * o.y; v.z += w1 * o.z; v.w += w1 * o.w;
    }
    ((float4*)(out + (size_t)tok * H_DIM))[t] = v;
}

// ---------------- launch --------------------------------------------------------
extern "C" void kernel_launch(void* const* d_in, const int* in_sizes, int n_in,
                              void* d_out, int out_size) {
    const float* x        = (const float*)d_in[0];
    const float* rms_w    = (const float*)d_in[1];
    const float* router_w = (const float*)d_in[2];
    const float* w1       = (const float*)d_in[3];
    const float* w2       = (const float*)d_in[4];
    float* out = (float*)d_out;

    static bool attr_done = false;
    if (!attr_done) {
        cudaFuncSetAttribute(k_gemm1, cudaFuncAttributeMaxDynamicSharedMemorySize, SMEM_SZ);
        cudaFuncSetAttribute(k_gemm2, cudaFuncAttributeMaxDynamicSharedMemorySize, SMEM_SZ);
        attr_done = true;
    }

    k_zero_counts<<<1, 64>>>();
    k_rmsnorm<<<S_TOK, 256>>>(x, rms_w);
    k_router<<<S_TOK / 64, 256>>>(router_w);
    k_gemm1<<<dim3(D_FF / 128, CAP / 128, N_EXP), 512, SMEM_SZ>>>(w1);
    k_gemm2<<<dim3(H_DIM / 128, CAP / 128, N_EXP), 512, SMEM_SZ>>>(w2);
    k_combine<<<S_TOK, 256>>>(x, out);
}

// round 4
// speedup vs baseline: 3.9630x; 1.0295x over previous
#include <cuda_runtime.h>
#include <cuda_bf16.h>
#include <math.h>
#include <stdint.h>

#define S_TOK 8192
#define H_DIM 1024
#define N_EXP 64
#define CAP 512
#define D_FF 2048
#define NROWS (N_EXP * CAP)  // 32768

// ---------------- scratch (device globals) ----------------------------------
__device__ float g_xn[(size_t)S_TOK * H_DIM];                 // 32 MB (router)
__device__ __nv_bfloat16 g_xn_hi[(size_t)S_TOK * H_DIM];      // 16 MB
__device__ __nv_bfloat16 g_xn_lo[(size_t)S_TOK * H_DIM];      // 16 MB
__device__ __nv_bfloat16 g_h_hi[(size_t)NROWS * D_FF];        // 128 MB
__device__ __nv_bfloat16 g_h_lo[(size_t)NROWS * D_FF];        // 128 MB
__device__ float g_od[(size_t)NROWS * H_DIM];                 // 128 MB
__device__ int   g_row_tok[NROWS];
__device__ int   g_count[N_EXP];
__device__ int   g_pair_idx[S_TOK * 2];
__device__ float g_pair_w[S_TOK * 2];

// ---------------- helpers -----------------------------------------------------
__device__ __forceinline__ uint32_t smem_u32(const void* p) {
    uint32_t a;
    asm("{ .reg .u64 t; cvta.to.shared.u64 t, %1; cvt.u32.u64 %0, t; }"
        : "=r"(a) : "l"(p));
    return a;
}
__device__ __forceinline__ void ldsm4(uint32_t* r, uint32_t addr) {
    asm volatile("ldmatrix.sync.aligned.m8n8.x4.shared.b16 {%0,%1,%2,%3}, [%4];"
                 : "=r"(r[0]), "=r"(r[1]), "=r"(r[2]), "=r"(r[3]) : "r"(addr));
}
__device__ __forceinline__ void mma_bf16(float* d, const uint32_t* a,
                                         uint32_t b0, uint32_t b1) {
    asm volatile("mma.sync.aligned.m16n8k16.row.col.f32.bf16.bf16.f32 "
                 "{%0,%1,%2,%3}, {%4,%5,%6,%7}, {%8,%9}, {%0,%1,%2,%3};"
                 : "+f"(d[0]), "+f"(d[1]), "+f"(d[2]), "+f"(d[3])
                 : "r"(a[0]), "r"(a[1]), "r"(a[2]), "r"(a[3]), "r"(b0), "r"(b1));
}
__device__ __forceinline__ uint32_t pack_bf2(float a, float b) {
    __nv_bfloat162 t = __floats2bfloat162_rn(a, b);
    return *reinterpret_cast<uint32_t*>(&t);
}
__device__ __forceinline__ float silu_f(float v) { return v / (1.0f + expf(-v)); }

// smem geometry: BK=32 bf16 per row = 64B payload, 80B stride (conflict-free)
#define RB 80
#define A_H 0
#define A_L (128 * RB)       // 10240
#define B_H (2 * 128 * RB)   // 20480
#define B_L (3 * 128 * RB)   // 30720
#define BUF (4 * 128 * RB)   // 40960
#define SMEM_SZ (2 * BUF)    // 81920

// ---------------- 0: zero expert counters ------------------------------------
__global__ void k_zero_counts() {
    if (threadIdx.x < N_EXP) g_count[threadIdx.x] = 0;
}

// ---------------- 1: RMSNorm (+ hi/lo split) ----------------------------------
__global__ void k_rmsnorm(const float* __restrict__ x, const float* __restrict__ w) {
    int tok = blockIdx.x;
    int t = threadIdx.x;
    float4 v = ((const float4*)(x + (size_t)tok * H_DIM))[t];
    float ss = v.x * v.x + v.y * v.y + v.z * v.z + v.w * v.w;
#pragma unroll
    for (int o = 16; o > 0; o >>= 1) ss += __shfl_xor_sync(0xffffffffu, ss, o);
    __shared__ float red[8];
    if ((t & 31) == 0) red[t >> 5] = ss;
    __syncthreads();
    float tot = red[0] + red[1] + red[2] + red[3] + red[4] + red[5] + red[6] + red[7];
    float scale = rsqrtf(tot * (1.0f / H_DIM) + 1e-6f);
    float4 wv = ((const float4*)w)[t];
    float4 o;
    o.x = v.x * scale * wv.x; o.y = v.y * scale * wv.y;
    o.z = v.z * scale * wv.z; o.w = v.w * scale * wv.w;
    ((float4*)(g_xn + (size_t)tok * H_DIM))[t] = o;
    float h0 = __bfloat162float(__float2bfloat16(o.x));
    float h1 = __bfloat162float(__float2bfloat16(o.y));
    float h2 = __bfloat162float(__float2bfloat16(o.z));
    float h3 = __bfloat162float(__float2bfloat16(o.w));
    uint2 H, L;
    H.x = pack_bf2(h0, h1); H.y = pack_bf2(h2, h3);
    L.x = pack_bf2(o.x - h0, o.y - h1); L.y = pack_bf2(o.z - h2, o.w - h3);
    *(uint2*)(g_xn_hi + (size_t)tok * H_DIM + t * 4) = H;
    *(uint2*)(g_xn_lo + (size_t)tok * H_DIM + t * 4) = L;
}

// ---------------- 2: router + top2 + slot assign ------------------------------
__global__ void k_router(const float* __restrict__ rw) {
    __shared__ float As[16][64];
    __shared__ float Bs[16][64];
    __shared__ float Ss[64][65];
    int t = threadIdx.x;
    int tok0 = blockIdx.x * 64;
    int ty = t >> 4, tx = t & 15;
    float acc[4][4];
#pragma unroll
    for (int i = 0; i < 4; i++)
#pragma unroll
        for (int j = 0; j < 4; j++) acc[i][j] = 0.0f;

    int lr = t >> 2;
    int lk = (t & 3) * 4;
    const float* ap = g_xn + (size_t)(tok0 + lr) * H_DIM + lk;
    const float* bp = rw + (size_t)lr * H_DIM + lk;

    for (int k0 = 0; k0 < H_DIM; k0 += 16) {
        float4 av = *(const float4*)(ap + k0);
        float4 bv = *(const float4*)(bp + k0);
        __syncthreads();
        As[lk + 0][lr] = av.x; As[lk + 1][lr] = av.y;
        As[lk + 2][lr] = av.z; As[lk + 3][lr] = av.w;
        Bs[lk + 0][lr] = bv.x; Bs[lk + 1][lr] = bv.y;
        Bs[lk + 2][lr] = bv.z; Bs[lk + 3][lr] = bv.w;
        __syncthreads();
#pragma unroll
        for (int kk = 0; kk < 16; kk++) {
            float a[4], b[4];
#pragma unroll
            for (int i = 0; i < 4; i++) a[i] = As[kk][ty * 4 + i];
#pragma unroll
            for (int j = 0; j < 4; j++) b[j] = Bs[kk][tx * 4 + j];
#pragma unroll
            for (int i = 0; i < 4; i++)
#pragma unroll
                for (int j = 0; j < 4; j++) acc[i][j] = fmaf(a[i], b[j], acc[i][j]);
        }
    }
    __syncthreads();
#pragma unroll
    for (int i = 0; i < 4; i++)
#pragma unroll
        for (int j = 0; j < 4; j++) Ss[ty * 4 + i][tx * 4 + j] = acc[i][j];
    __syncthreads();

    if (t < 64) {
        int tok = tok0 + t;
        float v1 = -1e30f, v2 = -1e30f;
        int i1 = 0, i2 = 0;
#pragma unroll 4
        for (int e = 0; e < N_EXP; e++) {
            float s = Ss[t][e];
            if (s > v1) { v2 = v1; i2 = i1; v1 = s; i1 = e; }
            else if (s > v2) { v2 = s; i2 = e; }
        }
        float ex = expf(v2 - v1);
        float wB = ex / (1.0f + ex);
        float wA = 1.0f - wB;

        int s1 = atomicAdd(&g_count[i1], 1);
        if (s1 < CAP) {
            g_row_tok[i1 * CAP + s1] = tok;
            g_pair_idx[tok * 2] = i1 * CAP + s1;
            g_pair_w[tok * 2] = wA;
        } else g_pair_idx[tok * 2] = -1;
        int s2 = atomicAdd(&g_count[i2], 1);
        if (s2 < CAP) {
            g_row_tok[i2 * CAP + s2] = tok;
            g_pair_idx[tok * 2 + 1] = i2 * CAP + s2;
            g_pair_w[tok * 2 + 1] = wB;
        } else g_pair_idx[tok * 2 + 1] = -1;
    }
}

// ---------------- convert float4 -> hi/lo bf16 uint2 --------------------------
__device__ __forceinline__ void split4(float4 v, uint2& H, uint2& L) {
    float h0 = __bfloat162float(__float2bfloat16(v.x));
    float h1 = __bfloat162float(__float2bfloat16(v.y));
    float h2 = __bfloat162float(__float2bfloat16(v.z));
    float h3 = __bfloat162float(__float2bfloat16(v.w));
    H.x = pack_bf2(h0, h1); H.y = pack_bf2(h2, h3);
    L.x = pack_bf2(v.x - h0, v.y - h1);
    L.y = pack_bf2(v.z - h2, v.w - h3);
}

// ---------------- GEMM1: h = silu(xn[gather] @ w1[e]^T) -----------------------
// CTA 128x128, 256 threads, 8 warps of 64x32, BK=32, double-buffered.
__global__ void __launch_bounds__(256, 2) k_gemm1(const float* __restrict__ w1) {
    int e = blockIdx.z;
    int cnt = min(g_count[e], CAP);
    int m0 = blockIdx.y * 128;
    if (m0 >= cnt) return;
    int n0 = blockIdx.x * 128;

    extern __shared__ char sm[];
    __shared__ int stok[128];
    int t = threadIdx.x, lane = t & 31, w = t >> 5;
    if (t < 128) {
        int s = m0 + t;
        stok[t] = (s < cnt) ? g_row_tok[e * CAP + s] : -1;
    }
    __syncthreads();

    int lr = t & 127;
    int lsg = t >> 7;  // 0/1 : which 16-element half of the 32-col chunk
    int atok = stok[lr];
    const __nv_bfloat16* ahp = g_xn_hi + ((atok >= 0) ? (size_t)atok * H_DIM : 0) + lsg * 16;
    const __nv_bfloat16* alp = g_xn_lo + ((atok >= 0) ? (size_t)atok * H_DIM : 0) + lsg * 16;
    bool avalid = atok >= 0;
    const float* bp = w1 + ((size_t)e * D_FF + n0 + lr) * H_DIM + lsg * 16;
    uint32_t sts = lr * RB + lsg * 32;

    int wm = (w & 1) * 64;
    int wn = (w >> 1) * 32;
    uint32_t smb = smem_u32(sm);
    uint32_t lm = (lane & 15) * RB + ((lane >> 4) << 4);
    uint32_t aoff = (wm + 0) * RB + lm + A_H;
    uint32_t boff = (wn + 0) * RB + lm + B_H;

    float acc[4][4][4];
#pragma unroll
    for (int mf = 0; mf < 4; mf++)
#pragma unroll
        for (int nf = 0; nf < 4; nf++)
#pragma unroll
            for (int k = 0; k < 4; k++) acc[mf][nf][k] = 0.0f;

    uint4 pah[2], pal[2];
    float4 pb[4];
    const uint4 z4 = make_uint4(0, 0, 0, 0);
#pragma unroll
    for (int j = 0; j < 2; j++) {
        pah[j] = avalid ? *(const uint4*)(ahp + j * 8) : z4;
        pal[j] = avalid ? *(const uint4*)(alp + j * 8) : z4;
    }
#pragma unroll
    for (int j = 0; j < 4; j++) pb[j] = *(const float4*)(bp + j * 4);

    const int NC = H_DIM / 32;  // 32
#pragma unroll 1
    for (int c = 0; c < NC; c++) {
        char* buf = sm + (c & 1) * BUF;
        *(uint4*)(buf + A_H + sts) = pah[0];
        *(uint4*)(buf + A_H + sts + 16) = pah[1];
        *(uint4*)(buf + A_L + sts) = pal[0];
        *(uint4*)(buf + A_L + sts + 16) = pal[1];
        {
            uint2 H0, L0, H1, L1, H2, L2, H3, L3;
            split4(pb[0], H0, L0); split4(pb[1], H1, L1);
            split4(pb[2], H2, L2); split4(pb[3], H3, L3);
            *(uint4*)(buf + B_H + sts) = make_uint4(H0.x, H0.y, H1.x, H1.y);
            *(uint4*)(buf + B_H + sts + 16) = make_uint4(H2.x, H2.y, H3.x, H3.y);
            *(uint4*)(buf + B_L + sts) = make_uint4(L0.x, L0.y, L1.x, L1.y);
            *(uint4*)(buf + B_L + sts + 16) = make_uint4(L2.x, L2.y, L3.x, L3.y);
        }
        __syncthreads();
        if (c + 1 < NC) {
#pragma unroll
            for (int j = 0; j < 2; j++) {
                pah[j] = avalid ? *(const uint4*)(ahp + (c + 1) * 32 + j * 8) : z4;
                pal[j] = avalid ? *(const uint4*)(alp + (c + 1) * 32 + j * 8) : z4;
            }
#pragma unroll
            for (int j = 0; j < 4; j++)
                pb[j] = *(const float4*)(bp + (c + 1) * 32 + j * 4);
        }
        uint32_t bb = smb + (c & 1) * BUF;
#pragma unroll
        for (int kk = 0; kk < 2; kk++) {
            uint32_t ko = kk * 32;
            uint32_t ah[4][4], bh[2][4];
#pragma unroll
            for (int mf = 0; mf < 4; mf++) ldsm4(ah[mf], bb + aoff + mf * (16 * RB) + ko);
#pragma unroll
            for (int g = 0; g < 2; g++) ldsm4(bh[g], bb + boff + g * (16 * RB) + ko);
#pragma unroll
            for (int mf = 0; mf < 4; mf++)
#pragma unroll
                for (int nf = 0; nf < 4; nf++)
                    mma_bf16(acc[mf][nf], ah[mf], bh[nf >> 1][nf & 1], bh[nf >> 1][(nf & 1) + 2]);
            uint32_t al[4][4];
#pragma unroll
            for (int mf = 0; mf < 4; mf++) ldsm4(al[mf], bb + aoff + A_L + mf * (16 * RB) + ko);
#pragma unroll
            for (int mf = 0; mf < 4; mf++)
#pragma unroll
                for (int nf = 0; nf < 4; nf++)
                    mma_bf16(acc[mf][nf], al[mf], bh[nf >> 1][nf & 1], bh[nf >> 1][(nf & 1) + 2]);
            uint32_t bl[2][4];
#pragma unroll
            for (int g = 0; g < 2; g++) ldsm4(bl[g], bb + boff + (B_L - B_H) + g * (16 * RB) + ko);
#pragma unroll
            for (int mf = 0; mf < 4; mf++)
#pragma unroll
                for (int nf = 0; nf < 4; nf++)
                    mma_bf16(acc[mf][nf], ah[mf], bl[nf >> 1][nf & 1], bl[nf >> 1][(nf & 1) + 2]);
        }
    }

    int rbase = m0 + wm + (lane >> 2);
    size_t eb = (size_t)e * CAP;
#pragma unroll
    for (int mf = 0; mf < 4; mf++) {
#pragma unroll
        for (int nf = 0; nf < 4; nf++) {
            int col = n0 + wn + nf * 8 + (lane & 3) * 2;
#pragma unroll
            for (int half = 0; half < 2; half++) {
                size_t r = eb + rbase + mf * 16 + half * 8;
                float s0 = silu_f(acc[mf][nf][half * 2]);
                float s1 = silu_f(acc[mf][nf][half * 2 + 1]);
                float h0 = __bfloat162float(__float2bfloat16(s0));
                float h1 = __bfloat162float(__float2bfloat16(s1));
                *(uint32_t*)(g_h_hi + r * D_FF + col) = pack_bf2(h0, h1);
                *(uint32_t*)(g_h_lo + r * D_FF + col) = pack_bf2(s0 - h0, s1 - h1);
            }
        }
    }
}

// ---------------- GEMM2: od = h @ w2[e]^T --------------------------------------
__global__ void __launch_bounds__(256, 2) k_gemm2(const float* __restrict__ w2) {
    int e = blockIdx.z;
    int cnt = min(g_count[e], CAP);
    int m0 = blockIdx.y * 128;
    if (m0 >= cnt) return;
    int n0 = blockIdx.x * 128;

    extern __shared__ char sm[];
    int t = threadIdx.x, lane = t & 31, w = t >> 5;

    int lr = t & 127;
    int lsg = t >> 7;
    size_t arow = ((size_t)e * CAP + m0 + lr) * D_FF + lsg * 16;
    const float* bp = w2 + ((size_t)e * H_DIM + n0 + lr) * D_FF + lsg * 16;
    uint32_t sts = lr * RB + lsg * 32;

    int wm = (w & 1) * 64;
    int wn = (w >> 1) * 32;
    uint32_t smb = smem_u32(sm);
    uint32_t lm = (lane & 15) * RB + ((lane >> 4) << 4);
    uint32_t aoff = wm * RB + lm + A_H;
    uint32_t boff = wn * RB + lm + B_H;

    float acc[4][4][4];
#pragma unroll
    for (int mf = 0; mf < 4; mf++)
#pragma unroll
        for (int nf = 0; nf < 4; nf++)
#pragma unroll
            for (int k = 0; k < 4; k++) acc[mf][nf][k] = 0.0f;

    uint4 pah[2], pal[2];
    float4 pb[4];
#pragma unroll
    for (int j = 0; j < 2; j++) {
        pah[j] = *(const uint4*)(g_h_hi + arow + j * 8);
        pal[j] = *(const uint4*)(g_h_lo + arow + j * 8);
    }
#pragma unroll
    for (int j = 0; j < 4; j++) pb[j] = *(const float4*)(bp + j * 4);

    const int NC = D_FF / 32;  // 64
#pragma unroll 1
    for (int c = 0; c < NC; c++) {
        char* buf = sm + (c & 1) * BUF;
        *(uint4*)(buf + A_H + sts) = pah[0];
        *(uint4*)(buf + A_H + sts + 16) = pah[1];
        *(uint4*)(buf + A_L + sts) = pal[0];
        *(uint4*)(buf + A_L + sts + 16) = pal[1];
        {
            uint2 H0, L0, H1, L1, H2, L2, H3, L3;
            split4(pb[0], H0, L0); split4(pb[1], H1, L1);
            split4(pb[2], H2, L2); split4(pb[3], H3, L3);
            *(uint4*)(buf + B_H + sts) = make_uint4(H0.x, H0.y, H1.x, H1.y);
            *(uint4*)(buf + B_H + sts + 16) = make_uint4(H2.x, H2.y, H3.x, H3.y);
            *(uint4*)(buf + B_L + sts) = make_uint4(L0.x, L0.y, L1.x, L1.y);
            *(uint4*)(buf + B_L + sts + 16) = make_uint4(L2.x, L2.y, L3.x, L3.y);
        }
        __syncthreads();
        if (c + 1 < NC) {
#pragma unroll
            for (int j = 0; j < 2; j++) {
                pah[j] = *(const uint4*)(g_h_hi + arow + (c + 1) * 32 + j * 8);
                pal[j] = *(const uint4*)(g_h_lo + arow + (c + 1) * 32 + j * 8);
            }
#pragma unroll
            for (int j = 0; j < 4; j++)
                pb[j] = *(const float4*)(bp + (c + 1) * 32 + j * 4);
        }
        uint32_t bb = smb + (c & 1) * BUF;
#pragma unroll
        for (int kk = 0; kk < 2; kk++) {
            uint32_t ko = kk * 32;
            uint32_t ah[4][4], bh[2][4];
#pragma unroll
            for (int mf = 0; mf < 4; mf++) ldsm4(ah[mf], bb + aoff + mf * (16 * RB) + ko);
#pragma unroll
            for (int g = 0; g < 2; g++) ldsm4(bh[g], bb + boff + g * (16 * RB) + ko);
#pragma unroll
            for (int mf = 0; mf < 4; mf++)
#pragma unroll
                for (int nf = 0; nf < 4; nf++)
                    mma_bf16(acc[mf][nf], ah[mf], bh[nf >> 1][nf & 1], bh[nf >> 1][(nf & 1) + 2]);
            uint32_t al[4][4];
#pragma unroll
            for (int mf = 0; mf < 4; mf++) ldsm4(al[mf], bb + aoff + A_L + mf * (16 * RB) + ko);
#pragma unroll
            for (int mf = 0; mf < 4; mf++)
#pragma unroll
                for (int nf = 0; nf < 4; nf++)
                    mma_bf16(acc[mf][nf], al[mf], bh[nf >> 1][nf & 1], bh[nf >> 1][(nf & 1) + 2]);
            uint32_t bl[2][4];
#pragma unroll
            for (int g = 0; g < 2; g++) ldsm4(bl[g], bb + boff + (B_L - B_H) + g * (16 * RB) + ko);
#pragma unroll
            for (int mf = 0; mf < 4; mf++)
#pragma unroll
                for (int nf = 0; nf < 4; nf++)
                    mma_bf16(acc[mf][nf], ah[mf], bl[nf >> 1][nf & 1], bl[nf >> 1][(nf & 1) + 2]);
        }
    }

    int rbase = m0 + wm + (lane >> 2);
    size_t eb = (size_t)e * CAP;
#pragma unroll
    for (int mf = 0; mf < 4; mf++) {
#pragma unroll
        for (int nf = 0; nf < 4; nf++) {
            int col = n0 + wn + nf * 8 + (lane & 3) * 2;
#pragma unroll
            for (int half = 0; half < 2; half++) {
                size_t r = eb + rbase + mf * 16 + half * 8;
                *(float2*)(g_od + r * H_DIM + col) =
                    make_float2(acc[mf][nf][half * 2], acc[mf][nf][half * 2 + 1]);
            }
        }
    }
}

// ---------------- 5: combine ---------------------------------------------------
__global__ void k_combine(const float* __restrict__ x, float* __restrict__ out) {
    int tok = blockIdx.x;
    int t = threadIdx.x;
    int p0 = g_pair_idx[tok * 2];
    int p1 = g_pair_idx[tok * 2 + 1];
    float w0 = g_pair_w[tok * 2];
    float w1 = g_pair_w[tok * 2 + 1];
    float4 v = ((const float4*)(x + (size_t)tok * H_DIM))[t];
    if (p0 >= 0) {
        float4 o = ((const float4*)(g_od + (size_t)p0 * H_DIM))[t];
        v.x += w0 * o.x; v.y += w0 * o.y; v.z += w0 * o.z; v.w += w0 * o.w;
    }
    if (p1 >= 0) {
        float4 o = ((const float4*)(g_od + (size_t)p1 * H_DIM))[t];
        v.x += w1 * o.x; v.y += w1 * o.y; v.z += w1 * o.z; v.w += w1 * o.w;
    }
    ((float4*)(out + (size_t)tok * H_DIM))[t] = v;
}

// ---------------- launch --------------------------------------------------------
extern "C" void kernel_launch(void* const* d_in, const int* in_sizes, int n_in,
                              void* d_out, int out_size) {
    const float* x        = (const float*)d_in[0];
    const float* rms_w    = (const float*)d_in[1];
    const float* router_w = (const float*)d_in[2];
    const float* w1       = (const float*)d_in[3];
    const float* w2       = (const float*)d_in[4];
    float* out = (float*)d_out;

    static bool attr_done = false;
    if (!attr_done) {
        cudaFuncSetAttribute(k_gemm1, cudaFuncAttributeMaxDynamicSharedMemorySize, SMEM_SZ);
        cudaFuncSetAttribute(k_gemm2, cudaFuncAttributeMaxDynamicSharedMemorySize, SMEM_SZ);
        attr_done = true;
    }

    k_zero_counts<<<1, 64>>>();
    k_rmsnorm<<<S_TOK, 256>>>(x, rms_w);
    k_router<<<S_TOK / 64, 256>>>(router_w);
    k_gemm1<<<dim3(D_FF / 128, CAP / 128, N_EXP), 256, SMEM_SZ>>>(w1);
    k_gemm2<<<dim3(H_DIM / 128, CAP / 128, N_EXP), 256, SMEM_SZ>>>(w2);
    k_combine<<<S_TOK, 256>>>(x, out);
}

// round 5
// speedup vs baseline: 6.8852x; 1.7374x over previous
#include <cuda_runtime.h>
#include <cuda_fp16.h>
#include <math.h>
#include <stdint.h>

#define S_TOK 8192
#define H_DIM 1024
#define N_EXP 64
#define CAP 512
#define D_FF 2048
#define NROWS (N_EXP * CAP)                 // 32768
#define W_ELEMS ((size_t)N_EXP * D_FF * H_DIM)  // 134217728 (same for w1, w2)

// ---------------- scratch (device globals) ----------------------------------
__device__ float  g_xn[(size_t)S_TOK * H_DIM];          // 32 MB (router)
__device__ __half g_xn_hi[(size_t)S_TOK * H_DIM];       // 16 MB
__device__ __half g_xn_lo[(size_t)S_TOK * H_DIM];       // 16 MB
__device__ __half g_w1h[W_ELEMS];                        // 256 MB
__device__ __half g_w2h[W_ELEMS];                        // 256 MB
__device__ __half g_h_hi[(size_t)NROWS * D_FF];          // 128 MB
__device__ __half g_h_lo[(size_t)NROWS * D_FF];          // 128 MB
__device__ float  g_od[(size_t)NROWS * H_DIM];           // 128 MB
__device__ int    g_row_tok[NROWS];
__device__ int    g_count[N_EXP];
__device__ int    g_pair_idx[S_TOK * 2];
__device__ float  g_pair_w[S_TOK * 2];

// ---------------- helpers -----------------------------------------------------
__device__ __forceinline__ uint32_t smem_u32(const void* p) {
    uint32_t a;
    asm("{ .reg .u64 t; cvta.to.shared.u64 t, %1; cvt.u32.u64 %0, t; }"
        : "=r"(a) : "l"(p));
    return a;
}
__device__ __forceinline__ void ldsm4(uint32_t* r, uint32_t addr) {
    asm volatile("ldmatrix.sync.aligned.m8n8.x4.shared.b16 {%0,%1,%2,%3}, [%4];"
                 : "=r"(r[0]), "=r"(r[1]), "=r"(r[2]), "=r"(r[3]) : "r"(addr));
}
__device__ __forceinline__ void mma_f16(float* d, const uint32_t* a,
                                        uint32_t b0, uint32_t b1) {
    asm volatile("mma.sync.aligned.m16n8k16.row.col.f32.f16.f16.f32 "
                 "{%0,%1,%2,%3}, {%4,%5,%6,%7}, {%8,%9}, {%0,%1,%2,%3};"
                 : "+f"(d[0]), "+f"(d[1]), "+f"(d[2]), "+f"(d[3])
                 : "r"(a[0]), "r"(a[1]), "r"(a[2]), "r"(a[3]), "r"(b0), "r"(b1));
}
__device__ __forceinline__ void cp16(uint32_t dst, const void* src, uint32_t sz) {
    asm volatile("cp.async.cg.shared.global [%0], [%1], 16, %2;"
                 :: "r"(dst), "l"(src), "r"(sz) : "memory");
}
#define CP_COMMIT() asm volatile("cp.async.commit_group;" ::: "memory")
#define CP_WAIT1()  asm volatile("cp.async.wait_group 1;" ::: "memory")

__device__ __forceinline__ uint32_t pack_h2(float a, float b) {
    __half2 t = __floats2half2_rn(a, b);
    return *reinterpret_cast<uint32_t*>(&t);
}
__device__ __forceinline__ float silu_f(float v) { return v / (1.0f + expf(-v)); }

// smem geometry: BK=32 fp16 per row = 64B payload, 80B stride (conflict-free)
#define RB 80
#define A_H 0
#define A_L (128 * RB)        // 10240
#define B_H (2 * 128 * RB)    // 20480
#define STAGE (3 * 128 * RB)  // 30720
#define SMEM_SZ (3 * STAGE)   // 92160 (3-stage pipeline)

// ---------------- 0: zero expert counters ------------------------------------
__global__ void k_zero_counts() {
    if (threadIdx.x < N_EXP) g_count[threadIdx.x] = 0;
}

// ---------------- 0b: convert weights fp32 -> fp16 ----------------------------
__global__ void k_cvt_w(const float* __restrict__ w1, const float* __restrict__ w2) {
    size_t i = ((size_t)blockIdx.x * blockDim.x + threadIdx.x) * 4;
    if (i >= W_ELEMS) return;
    float4 a = *(const float4*)(w1 + i);
    float4 b = *(const float4*)(w2 + i);
    uint2 ha, hb;
    ha.x = pack_h2(a.x, a.y); ha.y = pack_h2(a.z, a.w);
    hb.x = pack_h2(b.x, b.y); hb.y = pack_h2(b.z, b.w);
    *(uint2*)(g_w1h + i) = ha;
    *(uint2*)(g_w2h + i) = hb;
}

// ---------------- 1: RMSNorm (+ fp16 hi/lo split) ------------------------------
__global__ void k_rmsnorm(const float* __restrict__ x, const float* __restrict__ w) {
    int tok = blockIdx.x;
    int t = threadIdx.x;
    float4 v = ((const float4*)(x + (size_t)tok * H_DIM))[t];
    float ss = v.x * v.x + v.y * v.y + v.z * v.z + v.w * v.w;
#pragma unroll
    for (int o = 16; o > 0; o >>= 1) ss += __shfl_xor_sync(0xffffffffu, ss, o);
    __shared__ float red[8];
    if ((t & 31) == 0) red[t >> 5] = ss;
    __syncthreads();
    float tot = red[0] + red[1] + red[2] + red[3] + red[4] + red[5] + red[6] + red[7];
    float scale = rsqrtf(tot * (1.0f / H_DIM) + 1e-6f);
    float4 wv = ((const float4*)w)[t];
    float4 o;
    o.x = v.x * scale * wv.x; o.y = v.y * scale * wv.y;
    o.z = v.z * scale * wv.z; o.w = v.w * scale * wv.w;
    ((float4*)(g_xn + (size_t)tok * H_DIM))[t] = o;
    float h0 = __half2float(__float2half_rn(o.x));
    float h1 = __half2float(__float2half_rn(o.y));
    float h2 = __half2float(__float2half_rn(o.z));
    float h3 = __half2float(__float2half_rn(o.w));
    uint2 H, L;
    H.x = pack_h2(h0, h1); H.y = pack_h2(h2, h3);
    L.x = pack_h2(o.x - h0, o.y - h1); L.y = pack_h2(o.z - h2, o.w - h3);
    *(uint2*)(g_xn_hi + (size_t)tok * H_DIM + t * 4) = H;
    *(uint2*)(g_xn_lo + (size_t)tok * H_DIM + t * 4) = L;
}

// ---------------- 2: router + top2 + slot assign ------------------------------
__global__ void k_router(const float* __restrict__ rw) {
    __shared__ float As[16][64];
    __shared__ float Bs[16][64];
    __shared__ float Ss[64][65];
    int t = threadIdx.x;
    int tok0 = blockIdx.x * 64;
    int ty = t >> 4, tx = t & 15;
    float acc[4][4];
#pragma unroll
    for (int i = 0; i < 4; i++)
#pragma unroll
        for (int j = 0; j < 4; j++) acc[i][j] = 0.0f;

    int lr = t >> 2;
    int lk = (t & 3) * 4;
    const float* ap = g_xn + (size_t)(tok0 + lr) * H_DIM + lk;
    const float* bp = rw + (size_t)lr * H_DIM + lk;

    for (int k0 = 0; k0 < H_DIM; k0 += 16) {
        float4 av = *(const float4*)(ap + k0);
        float4 bv = *(const float4*)(bp + k0);
        __syncthreads();
        As[lk + 0][lr] = av.x; As[lk + 1][lr] = av.y;
        As[lk + 2][lr] = av.z; As[lk + 3][lr] = av.w;
        Bs[lk + 0][lr] = bv.x; Bs[lk + 1][lr] = bv.y;
        Bs[lk + 2][lr] = bv.z; Bs[lk + 3][lr] = bv.w;
        __syncthreads();
#pragma unroll
        for (int kk = 0; kk < 16; kk++) {
            float a[4], b[4];
#pragma unroll
            for (int i = 0; i < 4; i++) a[i] = As[kk][ty * 4 + i];
#pragma unroll
            for (int j = 0; j < 4; j++) b[j] = Bs[kk][tx * 4 + j];
#pragma unroll
            for (int i = 0; i < 4; i++)
#pragma unroll
                for (int j = 0; j < 4; j++) acc[i][j] = fmaf(a[i], b[j], acc[i][j]);
        }
    }
    __syncthreads();
#pragma unroll
    for (int i = 0; i < 4; i++)
#pragma unroll
        for (int j = 0; j < 4; j++) Ss[ty * 4 + i][tx * 4 + j] = acc[i][j];
    __syncthreads();

    if (t < 64) {
        int tok = tok0 + t;
        float v1 = -1e30f, v2 = -1e30f;
        int i1 = 0, i2 = 0;
#pragma unroll 4
        for (int e = 0; e < N_EXP; e++) {
            float s = Ss[t][e];
            if (s > v1) { v2 = v1; i2 = i1; v1 = s; i1 = e; }
            else if (s > v2) { v2 = s; i2 = e; }
        }
        float ex = expf(v2 - v1);
        float wB = ex / (1.0f + ex);
        float wA = 1.0f - wB;

        int s1 = atomicAdd(&g_count[i1], 1);
        if (s1 < CAP) {
            g_row_tok[i1 * CAP + s1] = tok;
            g_pair_idx[tok * 2] = i1 * CAP + s1;
            g_pair_w[tok * 2] = wA;
        } else g_pair_idx[tok * 2] = -1;
        int s2 = atomicAdd(&g_count[i2], 1);
        if (s2 < CAP) {
            g_row_tok[i2 * CAP + s2] = tok;
            g_pair_idx[tok * 2 + 1] = i2 * CAP + s2;
            g_pair_w[tok * 2 + 1] = wB;
        } else g_pair_idx[tok * 2 + 1] = -1;
    }
}

// ---------------- GEMM core: fp16 2-term, cp.async 3-stage --------------------
// CTA 128x128, 256 threads, 8 warps of 64x32, BK=32 fp16.
// Per thread per stage: row = t>>1, half = t&1; 2x cp16 for each of Ah/Al/Bh.

// GEMM1: h = silu(xn[gather] @ w1[e]^T)
__global__ void __launch_bounds__(256, 2) k_gemm1() {
    int e = blockIdx.z;
    int cnt = min(g_count[e], CAP);
    int m0 = blockIdx.y * 128;
    if (m0 >= cnt) return;
    int n0 = blockIdx.x * 128;

    extern __shared__ char sm[];
    __shared__ int stok[128];
    int t = threadIdx.x, lane = t & 31, w = t >> 5;
    if (t < 128) {
        int s = m0 + t;
        stok[t] = (s < cnt) ? g_row_tok[e * CAP + s] : -1;
    }
    __syncthreads();

    int row = t >> 1;
    int half = t & 1;
    int atok = stok[row];
    uint32_t asz = (atok >= 0) ? 16u : 0u;
    const __half* ah_src = g_xn_hi + ((atok >= 0) ? (size_t)atok * H_DIM : 0) + half * 16;
    const __half* al_src = g_xn_lo + ((atok >= 0) ? (size_t)atok * H_DIM : 0) + half * 16;
    const __half* b_src = g_w1h + ((size_t)e * D_FF + n0 + row) * H_DIM + half * 16;
    uint32_t smb = smem_u32(sm);
    uint32_t sts = row * RB + half * 32;

    int wm = (w & 1) * 64;
    int wn = (w >> 1) * 32;
    uint32_t lm = (lane & 15) * RB + ((lane >> 4) << 4);
    uint32_t aoff = A_H + wm * RB + lm;
    uint32_t boff = B_H + wn * RB + lm;

    const int NC = H_DIM / 32;  // 32

    // prologue: stages 0, 1
#pragma unroll
    for (int s = 0; s < 2; s++) {
        uint32_t d = smb + s * STAGE + sts;
        cp16(d + A_H, ah_src + s * 32, asz);
        cp16(d + A_H + 16, ah_src + s * 32 + 8, asz);
        cp16(d + A_L, al_src + s * 32, asz);
        cp16(d + A_L + 16, al_src + s * 32 + 8, asz);
        cp16(d + B_H, b_src + s * 32, 16);
        cp16(d + B_H + 16, b_src + s * 32 + 8, 16);
        CP_COMMIT();
    }

    float acc[4][4][4];
#pragma unroll
    for (int mf = 0; mf < 4; mf++)
#pragma unroll
        for (int nf = 0; nf < 4; nf++)
#pragma unroll
            for (int k = 0; k < 4; k++) acc[mf][nf][k] = 0.0f;

    int bufc = 0;
#pragma unroll 1
    for (int c = 0; c < NC; c++) {
        CP_WAIT1();
        __syncthreads();
        if (c + 2 < NC) {
            int s = c + 2;
            int bs = s % 3;
            uint32_t d = smb + bs * STAGE + sts;
            cp16(d + A_H, ah_src + s * 32, asz);
            cp16(d + A_H + 16, ah_src + s * 32 + 8, asz);
            cp16(d + A_L, al_src + s * 32, asz);
            cp16(d + A_L + 16, al_src + s * 32 + 8, asz);
            cp16(d + B_H, b_src + s * 32, 16);
            cp16(d + B_H + 16, b_src + s * 32 + 8, 16);
        }
        CP_COMMIT();
        uint32_t bb = smb + bufc * STAGE;
        bufc = (bufc == 2) ? 0 : bufc + 1;
#pragma unroll
        for (int kk = 0; kk < 2; kk++) {
            uint32_t ko = kk * 32;
            uint32_t ah[4][4], bh[2][4];
#pragma unroll
            for (int mf = 0; mf < 4; mf++) ldsm4(ah[mf], bb + aoff + mf * (16 * RB) + ko);
#pragma unroll
            for (int g = 0; g < 2; g++) ldsm4(bh[g], bb + boff + g * (16 * RB) + ko);
#pragma unroll
            for (int mf = 0; mf < 4; mf++)
#pragma unroll
                for (int nf = 0; nf < 4; nf++)
                    mma_f16(acc[mf][nf], ah[mf], bh[nf >> 1][nf & 1], bh[nf >> 1][(nf & 1) + 2]);
            uint32_t al[4][4];
#pragma unroll
            for (int mf = 0; mf < 4; mf++) ldsm4(al[mf], bb + aoff + (A_L - A_H) + mf * (16 * RB) + ko);
#pragma unroll
            for (int mf = 0; mf < 4; mf++)
#pragma unroll
                for (int nf = 0; nf < 4; nf++)
                    mma_f16(acc[mf][nf], al[mf], bh[nf >> 1][nf & 1], bh[nf >> 1][(nf & 1) + 2]);
        }
    }

    // epilogue: silu, split hi/lo fp16, store
    int rbase = m0 + wm + (lane >> 2);
    size_t eb = (size_t)e * CAP;
#pragma unroll
    for (int mf = 0; mf < 4; mf++) {
#pragma unroll
        for (int nf = 0; nf < 4; nf++) {
            int col = n0 + wn + nf * 8 + (lane & 3) * 2;
#pragma unroll
            for (int hh = 0; hh < 2; hh++) {
                size_t r = eb + rbase + mf * 16 + hh * 8;
                float s0 = silu_f(acc[mf][nf][hh * 2]);
                float s1 = silu_f(acc[mf][nf][hh * 2 + 1]);
                float h0 = __half2float(__float2half_rn(s0));
                float h1 = __half2float(__float2half_rn(s1));
                *(uint32_t*)(g_h_hi + r * D_FF + col) = pack_h2(h0, h1);
                *(uint32_t*)(g_h_lo + r * D_FF + col) = pack_h2(s0 - h0, s1 - h1);
            }
        }
    }
}

// GEMM2: od = h @ w2[e]^T
__global__ void __launch_bounds__(256, 2) k_gemm2() {
    int e = blockIdx.z;
    int cnt = min(g_count[e], CAP);
    int m0 = blockIdx.y * 128;
    if (m0 >= cnt) return;
    int n0 = blockIdx.x * 128;

    extern __shared__ char sm[];
    int t = threadIdx.x, lane = t & 31, w = t >> 5;

    int row = t >> 1;
    int half = t & 1;
    size_t arow = ((size_t)e * CAP + m0 + row) * D_FF + half * 16;
    const __half* ah_src = g_h_hi + arow;
    const __half* al_src = g_h_lo + arow;
    const __half* b_src = g_w2h + ((size_t)e * H_DIM + n0 + row) * D_FF + half * 16;
    uint32_t smb = smem_u32(sm);
    uint32_t sts = row * RB + half * 32;

    int wm = (w & 1) * 64;
    int wn = (w >> 1) * 32;
    uint32_t lm = (lane & 15) * RB + ((lane >> 4) << 4);
    uint32_t aoff = A_H + wm * RB + lm;
    uint32_t boff = B_H + wn * RB + lm;

    const int NC = D_FF / 32;  // 64

#pragma unroll
    for (int s = 0; s < 2; s++) {
        uint32_t d = smb + s * STAGE + sts;
        cp16(d + A_H, ah_src + s * 32, 16);
        cp16(d + A_H + 16, ah_src + s * 32 + 8, 16);
        cp16(d + A_L, al_src + s * 32, 16);
        cp16(d + A_L + 16, al_src + s * 32 + 8, 16);
        cp16(d + B_H, b_src + s * 32, 16);
        cp16(d + B_H + 16, b_src + s * 32 + 8, 16);
        CP_COMMIT();
    }

    float acc[4][4][4];
#pragma unroll
    for (int mf = 0; mf < 4; mf++)
#pragma unroll
        for (int nf = 0; nf < 4; nf++)
#pragma unroll
            for (int k = 0; k < 4; k++) acc[mf][nf][k] = 0.0f;

    int bufc = 0;
#pragma unroll 1
    for (int c = 0; c < NC; c++) {
        CP_WAIT1();
        __syncthreads();
        if (c + 2 < NC) {
            int s = c + 2;
            int bs = s % 3;
            uint32_t d = smb + bs * STAGE + sts;
            cp16(d + A_H, ah_src + s * 32, 16);
            cp16(d + A_H + 16, ah_src + s * 32 + 8, 16);
            cp16(d + A_L, al_src + s * 32, 16);
            cp16(d + A_L + 16, al_src + s * 32 + 8, 16);
            cp16(d + B_H, b_src + s * 32, 16);
            cp16(d + B_H + 16, b_src + s * 32 + 8, 16);
        }
        CP_COMMIT();
        uint32_t bb = smb + bufc * STAGE;
        bufc = (bufc == 2) ? 0 : bufc + 1;
#pragma unroll
        for (int kk = 0; kk < 2; kk++) {
            uint32_t ko = kk * 32;
            uint32_t ah[4][4], bh[2][4];
#pragma unroll
            for (int mf = 0; mf < 4; mf++) ldsm4(ah[mf], bb + aoff + mf * (16 * RB) + ko);
#pragma unroll
            for (int g = 0; g < 2; g++) ldsm4(bh[g], bb + boff + g * (16 * RB) + ko);
#pragma unroll
            for (int mf = 0; mf < 4; mf++)
#pragma unroll
                for (int nf = 0; nf < 4; nf++)
                    mma_f16(acc[mf][nf], ah[mf], bh[nf >> 1][nf & 1], bh[nf >> 1][(nf & 1) + 2]);
            uint32_t al[4][4];
#pragma unroll
            for (int mf = 0; mf < 4; mf++) ldsm4(al[mf], bb + aoff + (A_L - A_H) + mf * (16 * RB) + ko);
#pragma unroll
            for (int mf = 0; mf < 4; mf++)
#pragma unroll
                for (int nf = 0; nf < 4; nf++)
                    mma_f16(acc[mf][nf], al[mf], bh[nf >> 1][nf & 1], bh[nf >> 1][(nf & 1) + 2]);
        }
    }

    int rbase = m0 + wm + (lane >> 2);
    size_t eb = (size_t)e * CAP;
#pragma unroll
    for (int mf = 0; mf < 4; mf++) {
#pragma unroll
        for (int nf = 0; nf < 4; nf++) {
            int col = n0 + wn + nf * 8 + (lane & 3) * 2;
#pragma unroll
            for (int hh = 0; hh < 2; hh++) {
                size_t r = eb + rbase + mf * 16 + hh * 8;
                *(float2*)(g_od + r * H_DIM + col) =
                    make_float2(acc[mf][nf][hh * 2], acc[mf][nf][hh * 2 + 1]);
            }
        }
    }
}

// ---------------- 5: combine ---------------------------------------------------
__global__ void k_combine(const float* __restrict__ x, float* __restrict__ out) {
    int tok = blockIdx.x;
    int t = threadIdx.x;
    int p0 = g_pair_idx[tok * 2];
    int p1 = g_pair_idx[tok * 2 + 1];
    float w0 = g_pair_w[tok * 2];
    float w1 = g_pair_w[tok * 2 + 1];
    float4 v = ((const float4*)(x + (size_t)tok * H_DIM))[t];
    if (p0 >= 0) {
        float4 o = ((const float4*)(g_od + (size_t)p0 * H_DIM))[t];
        v.x += w0 * o.x; v.y += w0 * o.y; v.z += w0 * o.z; v.w += w0 * o.w;
    }
    if (p1 >= 0) {
        float4 o = ((const float4*)(g_od + (size_t)p1 * H_DIM))[t];
        v.x += w1 * o.x; v.y += w1 * o.y; v.z += w1 * o.z; v.w += w1 * o.w;
    }
    ((float4*)(out + (size_t)tok * H_DIM))[t] = v;
}

// ---------------- launch --------------------------------------------------------
extern "C" void kernel_launch(void* const* d_in, const int* in_sizes, int n_in,
                              void* d_out, int out_size) {
    const float* x        = (const float*)d_in[0];
    const float* rms_w    = (const float*)d_in[1];
    const float* router_w = (const float*)d_in[2];
    const float* w1       = (const float*)d_in[3];
    const float* w2       = (const float*)d_in[4];
    float* out = (float*)d_out;

    static bool attr_done = false;
    if (!attr_done) {
        cudaFuncSetAttribute(k_gemm1, cudaFuncAttributeMaxDynamicSharedMemorySize, SMEM_SZ);
        cudaFuncSetAttribute(k_gemm2, cudaFuncAttributeMaxDynamicSharedMemorySize, SMEM_SZ);
        attr_done = true;
    }

    k_zero_counts<<<1, 64>>>();
    k_cvt_w<<<(unsigned)(W_ELEMS / 4 / 256), 256>>>(w1, w2);
    k_rmsnorm<<<S_TOK, 256>>>(x, rms_w);
    k_router<<<S_TOK / 64, 256>>>(router_w);
    k_gemm1<<<dim3(D_FF / 128, CAP / 128, N_EXP), 256, SMEM_SZ>>>();
    k_gemm2<<<dim3(H_DIM / 128, CAP / 128, N_EXP), 256, SMEM_SZ>>>();
    k_combine<<<S_TOK, 256>>>(x, out);
}

// round 6
// speedup vs baseline: 8.0474x; 1.1688x over previous
#include <cuda_runtime.h>
#include <cuda_fp16.h>
#include <math.h>
#include <stdint.h>

#define S_TOK 8192
#define H_DIM 1024
#define N_EXP 64
#define CAP 512
#define D_FF 2048
#define NROWS (N_EXP * CAP)  // 32768

// ---------------- scratch (device globals) ----------------------------------
__device__ float  g_xn[(size_t)S_TOK * H_DIM];          // 32 MB (router)
__device__ __half g_xn_hi[(size_t)S_TOK * H_DIM];       // 16 MB
__device__ __half g_xn_lo[(size_t)S_TOK * H_DIM];       // 16 MB
__device__ __half g_h_hi[(size_t)NROWS * D_FF];         // 128 MB
__device__ __half g_h_lo[(size_t)NROWS * D_FF];         // 128 MB
__device__ float  g_od[(size_t)NROWS * H_DIM];          // 128 MB
__device__ int    g_row_tok[NROWS];
__device__ int    g_count[N_EXP];
__device__ int    g_pair_idx[S_TOK * 2];
__device__ float  g_pair_w[S_TOK * 2];

// ---------------- helpers -----------------------------------------------------
__device__ __forceinline__ uint32_t smem_u32(const void* p) {
    uint32_t a;
    asm("{ .reg .u64 t; cvta.to.shared.u64 t, %1; cvt.u32.u64 %0, t; }"
        : "=r"(a) : "l"(p));
    return a;
}
__device__ __forceinline__ void ldsm4(uint32_t* r, uint32_t addr) {
    asm volatile("ldmatrix.sync.aligned.m8n8.x4.shared.b16 {%0,%1,%2,%3}, [%4];"
                 : "=r"(r[0]), "=r"(r[1]), "=r"(r[2]), "=r"(r[3]) : "r"(addr));
}
__device__ __forceinline__ void mma_f16(float* d, const uint32_t* a,
                                        uint32_t b0, uint32_t b1) {
    asm volatile("mma.sync.aligned.m16n8k16.row.col.f32.f16.f16.f32 "
                 "{%0,%1,%2,%3}, {%4,%5,%6,%7}, {%8,%9}, {%0,%1,%2,%3};"
                 : "+f"(d[0]), "+f"(d[1]), "+f"(d[2]), "+f"(d[3])
                 : "r"(a[0]), "r"(a[1]), "r"(a[2]), "r"(a[3]), "r"(b0), "r"(b1));
}
__device__ __forceinline__ void cp16(uint32_t dst, const void* src, uint32_t sz) {
    asm volatile("cp.async.cg.shared.global [%0], [%1], 16, %2;"
                 :: "r"(dst), "l"(src), "r"(sz) : "memory");
}
#define CP_COMMIT() asm volatile("cp.async.commit_group;" ::: "memory")
#define CP_WAIT1()  asm volatile("cp.async.wait_group 1;" ::: "memory")

__device__ __forceinline__ uint32_t pack_h2(float a, float b) {
    __half2 t = __floats2half2_rn(a, b);
    return *reinterpret_cast<uint32_t*>(&t);
}
__device__ __forceinline__ float silu_f(float v) { return v / (1.0f + expf(-v)); }

// smem geometry: BK=32 fp16 per row = 64B payload, 80B stride (conflict-free)
#define RB 80
#define A_H 0
#define A_L (128 * RB)        // 10240
#define B_H (2 * 128 * RB)    // 20480
#define STAGE (3 * 128 * RB)  // 30720
#define SMEM_SZ (3 * STAGE)   // 92160 (3-stage pipeline)

// ---------------- 0: zero expert counters ------------------------------------
__global__ void k_zero_counts() {
    if (threadIdx.x < N_EXP) g_count[threadIdx.x] = 0;
}

// ---------------- 1: RMSNorm (+ fp16 hi/lo split) ------------------------------
__global__ void k_rmsnorm(const float* __restrict__ x, const float* __restrict__ w) {
    int tok = blockIdx.x;
    int t = threadIdx.x;
    float4 v = ((const float4*)(x + (size_t)tok * H_DIM))[t];
    float ss = v.x * v.x + v.y * v.y + v.z * v.z + v.w * v.w;
#pragma unroll
    for (int o = 16; o > 0; o >>= 1) ss += __shfl_xor_sync(0xffffffffu, ss, o);
    __shared__ float red[8];
    if ((t & 31) == 0) red[t >> 5] = ss;
    __syncthreads();
    float tot = red[0] + red[1] + red[2] + red[3] + red[4] + red[5] + red[6] + red[7];
    float scale = rsqrtf(tot * (1.0f / H_DIM) + 1e-6f);
    float4 wv = ((const float4*)w)[t];
    float4 o;
    o.x = v.x * scale * wv.x; o.y = v.y * scale * wv.y;
    o.z = v.z * scale * wv.z; o.w = v.w * scale * wv.w;
    ((float4*)(g_xn + (size_t)tok * H_DIM))[t] = o;
    float h0 = __half2float(__float2half_rn(o.x));
    float h1 = __half2float(__float2half_rn(o.y));
    float h2 = __half2float(__float2half_rn(o.z));
    float h3 = __half2float(__float2half_rn(o.w));
    uint2 H, L;
    H.x = pack_h2(h0, h1); H.y = pack_h2(h2, h3);
    L.x = pack_h2(o.x - h0, o.y - h1); L.y = pack_h2(o.z - h2, o.w - h3);
    *(uint2*)(g_xn_hi + (size_t)tok * H_DIM + t * 4) = H;
    *(uint2*)(g_xn_lo + (size_t)tok * H_DIM + t * 4) = L;
}

// ---------------- 2: router + top2 + slot assign ------------------------------
// 256 blocks x 32 tokens. fp32 (expert choice must match fp32 reference).
__global__ void k_router(const float* __restrict__ rw) {
    __shared__ float As[16][32];
    __shared__ float Bs[16][64];
    __shared__ float Ss[32][65];
    int t = threadIdx.x;
    int tok0 = blockIdx.x * 32;
    int ty = t >> 4, tx = t & 15;  // ty: 2 rows each, tx: 4 cols each
    float acc[2][4];
#pragma unroll
    for (int i = 0; i < 2; i++)
#pragma unroll
        for (int j = 0; j < 4; j++) acc[i][j] = 0.0f;

    int lrA = t >> 3;          // 0..31
    int lkA = (t & 7) * 2;     // 0..14
    int lrB = t >> 2;          // 0..63
    int lkB = (t & 3) * 4;     // 0..12
    const float* ap = g_xn + (size_t)(tok0 + lrA) * H_DIM + lkA;
    const float* bp = rw + (size_t)lrB * H_DIM + lkB;

    for (int k0 = 0; k0 < H_DIM; k0 += 16) {
        float2 av = *(const float2*)(ap + k0);
        float4 bv = *(const float4*)(bp + k0);
        __syncthreads();
        As[lkA + 0][lrA] = av.x; As[lkA + 1][lrA] = av.y;
        Bs[lkB + 0][lrB] = bv.x; Bs[lkB + 1][lrB] = bv.y;
        Bs[lkB + 2][lrB] = bv.z; Bs[lkB + 3][lrB] = bv.w;
        __syncthreads();
#pragma unroll
        for (int kk = 0; kk < 16; kk++) {
            float a[2], b[4];
#pragma unroll
            for (int i = 0; i < 2; i++) a[i] = As[kk][ty * 2 + i];
#pragma unroll
            for (int j = 0; j < 4; j++) b[j] = Bs[kk][tx * 4 + j];
#pragma unroll
            for (int i = 0; i < 2; i++)
#pragma unroll
                for (int j = 0; j < 4; j++) acc[i][j] = fmaf(a[i], b[j], acc[i][j]);
        }
    }
    __syncthreads();
#pragma unroll
    for (int i = 0; i < 2; i++)
#pragma unroll
        for (int j = 0; j < 4; j++) Ss[ty * 2 + i][tx * 4 + j] = acc[i][j];
    __syncthreads();

    if (t < 32) {
        int tok = tok0 + t;
        float v1 = -1e30f, v2 = -1e30f;
        int i1 = 0, i2 = 0;
#pragma unroll 4
        for (int e = 0; e < N_EXP; e++) {
            float s = Ss[t][e];
            if (s > v1) { v2 = v1; i2 = i1; v1 = s; i1 = e; }
            else if (s > v2) { v2 = s; i2 = e; }
        }
        float ex = expf(v2 - v1);
        float wB = ex / (1.0f + ex);
        float wA = 1.0f - wB;

        int s1 = atomicAdd(&g_count[i1], 1);
        if (s1 < CAP) {
            g_row_tok[i1 * CAP + s1] = tok;
            g_pair_idx[tok * 2] = i1 * CAP + s1;
            g_pair_w[tok * 2] = wA;
        } else g_pair_idx[tok * 2] = -1;
        int s2 = atomicAdd(&g_count[i2], 1);
        if (s2 < CAP) {
            g_row_tok[i2 * CAP + s2] = tok;
            g_pair_idx[tok * 2 + 1] = i2 * CAP + s2;
            g_pair_w[tok * 2 + 1] = wB;
        } else g_pair_idx[tok * 2 + 1] = -1;
    }
}

// ---------------- GEMM core: fp16 2-term, A via cp.async, B fused fp32->fp16 --
// CTA 128x128, 256 threads, 8 warps of 64x32, BK=32, 3-stage smem ring.

// B prefetch/convert/store helpers (16 fp32 per thread per stage)
#define LDGB(dst, src, s)                                     \
    {                                                         \
        const float4* _p = (const float4*)((src) + (s) * 32); \
        dst[0] = _p[0]; dst[1] = _p[1];                        \
        dst[2] = _p[2]; dst[3] = _p[3];                        \
    }
#define STSB(buf, sts, br)                                                        \
    {                                                                             \
        *(uint4*)((buf) + B_H + (sts)) =                                          \
            make_uint4(pack_h2(br[0].x, br[0].y), pack_h2(br[0].z, br[0].w),      \
                       pack_h2(br[1].x, br[1].y), pack_h2(br[1].z, br[1].w));     \
        *(uint4*)((buf) + B_H + (sts) + 16) =                                     \
            make_uint4(pack_h2(br[2].x, br[2].y), pack_h2(br[2].z, br[2].w),      \
                       pack_h2(br[3].x, br[3].y), pack_h2(br[3].z, br[3].w));     \
    }

// GEMM1: h = silu(xn[gather] @ w1[e]^T)
__global__ void __launch_bounds__(256, 2) k_gemm1(const float* __restrict__ w1) {
    int e = blockIdx.z;
    int cnt = min(g_count[e], CAP);
    int m0 = blockIdx.y * 128;
    if (m0 >= cnt) return;
    int n0 = blockIdx.x * 128;

    extern __shared__ char sm[];
    __shared__ int stok[128];
    int t = threadIdx.x, lane = t & 31, w = t >> 5;
    if (t < 128) {
        int s = m0 + t;
        stok[t] = (s < cnt) ? g_row_tok[e * CAP + s] : -1;
    }
    __syncthreads();

    int row = t >> 1;
    int half = t & 1;
    int atok = stok[row];
    uint32_t asz = (atok >= 0) ? 16u : 0u;
    const __half* ah_src = g_xn_hi + ((atok >= 0) ? (size_t)atok * H_DIM : 0) + half * 16;
    const __half* al_src = g_xn_lo + ((atok >= 0) ? (size_t)atok * H_DIM : 0) + half * 16;
    const float* b_src = w1 + ((size_t)e * D_FF + n0 + row) * H_DIM + half * 16;
    uint32_t smb = smem_u32(sm);
    uint32_t sts = row * RB + half * 32;

    int wm = (w & 1) * 64;
    int wn = (w >> 1) * 32;
    uint32_t lm = (lane & 15) * RB + ((lane >> 4) << 4);
    uint32_t aoff = A_H + wm * RB + lm;
    uint32_t boff = B_H + wn * RB + lm;

    const int NC = H_DIM / 32;  // 32

    float4 br[4];
    // prologue: B s0 -> smem, B s1 -> regs, A s0/s1 via cp.async
    LDGB(br, b_src, 0);
    STSB(sm + 0 * STAGE, sts, br);
    LDGB(br, b_src, 1);
#pragma unroll
    for (int s = 0; s < 2; s++) {
        uint32_t d = smb + s * STAGE + sts;
        cp16(d + A_H, ah_src + s * 32, asz);
        cp16(d + A_H + 16, ah_src + s * 32 + 8, asz);
        cp16(d + A_L, al_src + s * 32, asz);
        cp16(d + A_L + 16, al_src + s * 32 + 8, asz);
        CP_COMMIT();
    }

    float acc[4][4][4];
#pragma unroll
    for (int mf = 0; mf < 4; mf++)
#pragma unroll
        for (int nf = 0; nf < 4; nf++)
#pragma unroll
            for (int k = 0; k < 4; k++) acc[mf][nf][k] = 0.0f;

    int bufc = 0;
#pragma unroll 1
    for (int c = 0; c < NC; c++) {
        CP_WAIT1();
        __syncthreads();
        if (c + 1 < NC) {
            int bs1 = (c + 1) % 3;
            STSB(sm + bs1 * STAGE, sts, br);
        }
        if (c + 2 < NC) {
            LDGB(br, b_src, c + 2);
            int bs2 = (c + 2) % 3;
            uint32_t d = smb + bs2 * STAGE + sts;
            cp16(d + A_H, ah_src + (c + 2) * 32, asz);
            cp16(d + A_H + 16, ah_src + (c + 2) * 32 + 8, asz);
            cp16(d + A_L, al_src + (c + 2) * 32, asz);
            cp16(d + A_L + 16, al_src + (c + 2) * 32 + 8, asz);
        }
        CP_COMMIT();
        uint32_t bb = smb + bufc * STAGE;
        bufc = (bufc == 2) ? 0 : bufc + 1;
#pragma unroll
        for (int kk = 0; kk < 2; kk++) {
            uint32_t ko = kk * 32;
            uint32_t ah[4][4], bh[2][4];
#pragma unroll
            for (int mf = 0; mf < 4; mf++) ldsm4(ah[mf], bb + aoff + mf * (16 * RB) + ko);
#pragma unroll
            for (int g = 0; g < 2; g++) ldsm4(bh[g], bb + boff + g * (16 * RB) + ko);
#pragma unroll
            for (int mf = 0; mf < 4; mf++)
#pragma unroll
                for (int nf = 0; nf < 4; nf++)
                    mma_f16(acc[mf][nf], ah[mf], bh[nf >> 1][nf & 1], bh[nf >> 1][(nf & 1) + 2]);
            uint32_t al[4][4];
#pragma unroll
            for (int mf = 0; mf < 4; mf++) ldsm4(al[mf], bb + aoff + (A_L - A_H) + mf * (16 * RB) + ko);
#pragma unroll
            for (int mf = 0; mf < 4; mf++)
#pragma unroll
                for (int nf = 0; nf < 4; nf++)
                    mma_f16(acc[mf][nf], al[mf], bh[nf >> 1][nf & 1], bh[nf >> 1][(nf & 1) + 2]);
        }
    }

    int rbase = m0 + wm + (lane >> 2);
    size_t eb = (size_t)e * CAP;
#pragma unroll
    for (int mf = 0; mf < 4; mf++) {
#pragma unroll
        for (int nf = 0; nf < 4; nf++) {
            int col = n0 + wn + nf * 8 + (lane & 3) * 2;
#pragma unroll
            for (int hh = 0; hh < 2; hh++) {
                size_t r = eb + rbase + mf * 16 + hh * 8;
                float s0 = silu_f(acc[mf][nf][hh * 2]);
                float s1 = silu_f(acc[mf][nf][hh * 2 + 1]);
                float h0 = __half2float(__float2half_rn(s0));
                float h1 = __half2float(__float2half_rn(s1));
                *(uint32_t*)(g_h_hi + r * D_FF + col) = pack_h2(h0, h1);
                *(uint32_t*)(g_h_lo + r * D_FF + col) = pack_h2(s0 - h0, s1 - h1);
            }
        }
    }
}

// GEMM2: od = h @ w2[e]^T
__global__ void __launch_bounds__(256, 2) k_gemm2(const float* __restrict__ w2) {
    int e = blockIdx.z;
    int cnt = min(g_count[e], CAP);
    int m0 = blockIdx.y * 128;
    if (m0 >= cnt) return;
    int n0 = blockIdx.x * 128;

    extern __shared__ char sm[];
    int t = threadIdx.x, lane = t & 31, w = t >> 5;

    int row = t >> 1;
    int half = t & 1;
    size_t arow = ((size_t)e * CAP + m0 + row) * D_FF + half * 16;
    const __half* ah_src = g_h_hi + arow;
    const __half* al_src = g_h_lo + arow;
    const float* b_src = w2 + ((size_t)e * H_DIM + n0 + row) * D_FF + half * 16;
    uint32_t smb = smem_u32(sm);
    uint32_t sts = row * RB + half * 32;

    int wm = (w & 1) * 64;
    int wn = (w >> 1) * 32;
    uint32_t lm = (lane & 15) * RB + ((lane >> 4) << 4);
    uint32_t aoff = A_H + wm * RB + lm;
    uint32_t boff = B_H + wn * RB + lm;

    const int NC = D_FF / 32;  // 64

    float4 br[4];
    LDGB(br, b_src, 0);
    STSB(sm + 0 * STAGE, sts, br);
    LDGB(br, b_src, 1);
#pragma unroll
    for (int s = 0; s < 2; s++) {
        uint32_t d = smb + s * STAGE + sts;
        cp16(d + A_H, ah_src + s * 32, 16);
        cp16(d + A_H + 16, ah_src + s * 32 + 8, 16);
        cp16(d + A_L, al_src + s * 32, 16);
        cp16(d + A_L + 16, al_src + s * 32 + 8, 16);
        CP_COMMIT();
    }

    float acc[4][4][4];
#pragma unroll
    for (int mf = 0; mf < 4; mf++)
#pragma unroll
        for (int nf = 0; nf < 4; nf++)
#pragma unroll
            for (int k = 0; k < 4; k++) acc[mf][nf][k] = 0.0f;

    int bufc = 0;
#pragma unroll 1
    for (int c = 0; c < NC; c++) {
        CP_WAIT1();
        __syncthreads();
        if (c + 1 < NC) {
            int bs1 = (c + 1) % 3;
            STSB(sm + bs1 * STAGE, sts, br);
        }
        if (c + 2 < NC) {
            LDGB(br, b_src, c + 2);
            int bs2 = (c + 2) % 3;
            uint32_t d = smb + bs2 * STAGE + sts;
            cp16(d + A_H, ah_src + (c + 2) * 32, 16);
            cp16(d + A_H + 16, ah_src + (c + 2) * 32 + 8, 16);
            cp16(d + A_L, al_src + (c + 2) * 32, 16);
            cp16(d + A_L + 16, al_src + (c + 2) * 32 + 8, 16);
        }
        CP_COMMIT();
        uint32_t bb = smb + bufc * STAGE;
        bufc = (bufc == 2) ? 0 : bufc + 1;
#pragma unroll
        for (int kk = 0; kk < 2; kk++) {
            uint32_t ko = kk * 32;
            uint32_t ah[4][4], bh[2][4];
#pragma unroll
            for (int mf = 0; mf < 4; mf++) ldsm4(ah[mf], bb + aoff + mf * (16 * RB) + ko);
#pragma unroll
            for (int g = 0; g < 2; g++) ldsm4(bh[g], bb + boff + g * (16 * RB) + ko);
#pragma unroll
            for (int mf = 0; mf < 4; mf++)
#pragma unroll
                for (int nf = 0; nf < 4; nf++)
                    mma_f16(acc[mf][nf], ah[mf], bh[nf >> 1][nf & 1], bh[nf >> 1][(nf & 1) + 2]);
            uint32_t al[4][4];
#pragma unroll
            for (int mf = 0; mf < 4; mf++) ldsm4(al[mf], bb + aoff + (A_L - A_H) + mf * (16 * RB) + ko);
#pragma unroll
            for (int mf = 0; mf < 4; mf++)
#pragma unroll
                for (int nf = 0; nf < 4; nf++)
                    mma_f16(acc[mf][nf], al[mf], bh[nf >> 1][nf & 1], bh[nf >> 1][(nf & 1) + 2]);
        }
    }

    int rbase = m0 + wm + (lane >> 2);
    size_t eb = (size_t)e * CAP;
#pragma unroll
    for (int mf = 0; mf < 4; mf++) {
#pragma unroll
        for (int nf = 0; nf < 4; nf++) {
            int col = n0 + wn + nf * 8 + (lane & 3) * 2;
#pragma unroll
            for (int hh = 0; hh < 2; hh++) {
                size_t r = eb + rbase + mf * 16 + hh * 8;
                *(float2*)(g_od + r * H_DIM + col) =
                    make_float2(acc[mf][nf][hh * 2], acc[mf][nf][hh * 2 + 1]);
            }
        }
    }
}

// ---------------- 5: combine ---------------------------------------------------
__global__ void k_combine(const float* __restrict__ x, float* __restrict__ out) {
    int tok = blockIdx.x;
    int t = threadIdx.x;
    int p0 = g_pair_idx[tok * 2];
    int p1 = g_pair_idx[tok * 2 + 1];
    float w0 = g_pair_w[tok * 2];
    float w1 = g_pair_w[tok * 2 + 1];
    float4 v = ((const float4*)(x + (size_t)tok * H_DIM))[t];
    if (p0 >= 0) {
        float4 o = ((const float4*)(g_od + (size_t)p0 * H_DIM))[t];
        v.x += w0 * o.x; v.y += w0 * o.y; v.z += w0 * o.z; v.w += w0 * o.w;
    }
    if (p1 >= 0) {
        float4 o = ((const float4*)(g_od + (size_t)p1 * H_DIM))[t];
        v.x += w1 * o.x; v.y += w1 * o.y; v.z += w1 * o.z; v.w += w1 * o.w;
    }
    ((float4*)(out + (size_t)tok * H_DIM))[t] = v;
}

// ---------------- launch --------------------------------------------------------
extern "C" void kernel_launch(void* const* d_in, const int* in_sizes, int n_in,
                              void* d_out, int out_size) {
    const float* x        = (const float*)d_in[0];
    const float* rms_w    = (const float*)d_in[1];
    const float* router_w = (const float*)d_in[2];
    const float* w1       = (const float*)d_in[3];
    const float* w2       = (const float*)d_in[4];
    float* out = (float*)d_out;

    static bool attr_done = false;
    if (!attr_done) {
        cudaFuncSetAttribute(k_gemm1, cudaFuncAttributeMaxDynamicSharedMemorySize, SMEM_SZ);
        cudaFuncSetAttribute(k_gemm2, cudaFuncAttributeMaxDynamicSharedMemorySize, SMEM_SZ);
        attr_done = true;
    }

    k_zero_counts<<<1, 64>>>();
    k_rmsnorm<<<S_TOK, 256>>>(x, rms_w);
    k_router<<<S_TOK / 32, 256>>>(router_w);
    k_gemm1<<<dim3(D_FF / 128, CAP / 128, N_EXP), 256, SMEM_SZ>>>(w1);
    k_gemm2<<<dim3(H_DIM / 128, CAP / 128, N_EXP), 256, SMEM_SZ>>>(w2);
    k_combine<<<S_TOK, 256>>>(x, out);
}

// round 7
// speedup vs baseline: 12.4625x; 1.5486x over previous
#include <cuda_runtime.h>
#include <cuda_fp16.h>
#include <math.h>
#include <stdint.h>

#define S_TOK 8192
#define H_DIM 1024
#define N_EXP 64
#define CAP 512
#define D_FF 2048
#define NROWS (N_EXP * CAP)  // 32768

// ---------------- scratch (device globals) ----------------------------------
__device__ float  g_xn[(size_t)S_TOK * H_DIM];    // 32 MB (router, fp32)
__device__ __half g_xnh[(size_t)S_TOK * H_DIM];   // 16 MB
__device__ __half g_hh[(size_t)NROWS * D_FF];     // 128 MB
__device__ float  g_od[(size_t)NROWS * H_DIM];    // 128 MB
__device__ int    g_row_tok[NROWS];
__device__ int    g_count[N_EXP];
__device__ int    g_pair_idx[S_TOK * 2];
__device__ float  g_pair_w[S_TOK * 2];

// ---------------- helpers -----------------------------------------------------
__device__ __forceinline__ uint32_t smem_u32(const void* p) {
    uint32_t a;
    asm("{ .reg .u64 t; cvta.to.shared.u64 t, %1; cvt.u32.u64 %0, t; }"
        : "=r"(a) : "l"(p));
    return a;
}
__device__ __forceinline__ void ldsm4(uint32_t* r, uint32_t addr) {
    asm volatile("ldmatrix.sync.aligned.m8n8.x4.shared.b16 {%0,%1,%2,%3}, [%4];"
                 : "=r"(r[0]), "=r"(r[1]), "=r"(r[2]), "=r"(r[3]) : "r"(addr));
}
__device__ __forceinline__ void mma_f16(float* d, const uint32_t* a,
                                        uint32_t b0, uint32_t b1) {
    asm volatile("mma.sync.aligned.m16n8k16.row.col.f32.f16.f16.f32 "
                 "{%0,%1,%2,%3}, {%4,%5,%6,%7}, {%8,%9}, {%0,%1,%2,%3};"
                 : "+f"(d[0]), "+f"(d[1]), "+f"(d[2]), "+f"(d[3])
                 : "r"(a[0]), "r"(a[1]), "r"(a[2]), "r"(a[3]), "r"(b0), "r"(b1));
}
__device__ __forceinline__ void cp16(uint32_t dst, const void* src, uint32_t sz) {
    asm volatile("cp.async.cg.shared.global [%0], [%1], 16, %2;"
                 :: "r"(dst), "l"(src), "r"(sz) : "memory");
}
#define CP_COMMIT() asm volatile("cp.async.commit_group;" ::: "memory")
#define CP_WAIT1()  asm volatile("cp.async.wait_group 1;" ::: "memory")

__device__ __forceinline__ uint32_t pack_h2(float a, float b) {
    __half2 t = __floats2half2_rn(a, b);
    return *reinterpret_cast<uint32_t*>(&t);
}
__device__ __forceinline__ float silu_f(float v) { return v / (1.0f + expf(-v)); }

// smem geometry: BK=32 fp16 per row = 64B payload, 80B stride (conflict-free)
#define RB 80
#define A_OFF 0
#define B_OFF (128 * RB)      // 10240
#define STAGE (2 * 128 * RB)  // 20480
#define SMEM_SZ (3 * STAGE)   // 61440 (3-stage pipeline)

// ---------------- 0: zero expert counters ------------------------------------
__global__ void k_zero_counts() {
    if (threadIdx.x < N_EXP) g_count[threadIdx.x] = 0;
}

// ---------------- 1: RMSNorm (+ fp16 round) ------------------------------------
__global__ void k_rmsnorm(const float* __restrict__ x, const float* __restrict__ w) {
    int tok = blockIdx.x;
    int t = threadIdx.x;
    float4 v = ((const float4*)(x + (size_t)tok * H_DIM))[t];
    float ss = v.x * v.x + v.y * v.y + v.z * v.z + v.w * v.w;
#pragma unroll
    for (int o = 16; o > 0; o >>= 1) ss += __shfl_xor_sync(0xffffffffu, ss, o);
    __shared__ float red[8];
    if ((t & 31) == 0) red[t >> 5] = ss;
    __syncthreads();
    float tot = red[0] + red[1] + red[2] + red[3] + red[4] + red[5] + red[6] + red[7];
    float scale = rsqrtf(tot * (1.0f / H_DIM) + 1e-6f);
    float4 wv = ((const float4*)w)[t];
    float4 o;
    o.x = v.x * scale * wv.x; o.y = v.y * scale * wv.y;
    o.z = v.z * scale * wv.z; o.w = v.w * scale * wv.w;
    ((float4*)(g_xn + (size_t)tok * H_DIM))[t] = o;
    uint2 H;
    H.x = pack_h2(o.x, o.y); H.y = pack_h2(o.z, o.w);
    *(uint2*)(g_xnh + (size_t)tok * H_DIM + t * 4) = H;
}

// ---------------- 2: router + top2 + slot assign ------------------------------
// 256 blocks x 32 tokens. fp32 (expert choice must match fp32 reference).
__global__ void k_router(const float* __restrict__ rw) {
    __shared__ float As[16][32];
    __shared__ float Bs[16][64];
    __shared__ float Ss[32][65];
    int t = threadIdx.x;
    int tok0 = blockIdx.x * 32;
    int ty = t >> 4, tx = t & 15;
    float acc[2][4];
#pragma unroll
    for (int i = 0; i < 2; i++)
#pragma unroll
        for (int j = 0; j < 4; j++) acc[i][j] = 0.0f;

    int lrA = t >> 3;
    int lkA = (t & 7) * 2;
    int lrB = t >> 2;
    int lkB = (t & 3) * 4;
    const float* ap = g_xn + (size_t)(tok0 + lrA) * H_DIM + lkA;
    const float* bp = rw + (size_t)lrB * H_DIM + lkB;

    for (int k0 = 0; k0 < H_DIM; k0 += 16) {
        float2 av = *(const float2*)(ap + k0);
        float4 bv = *(const float4*)(bp + k0);
        __syncthreads();
        As[lkA + 0][lrA] = av.x; As[lkA + 1][lrA] = av.y;
        Bs[lkB + 0][lrB] = bv.x; Bs[lkB + 1][lrB] = bv.y;
        Bs[lkB + 2][lrB] = bv.z; Bs[lkB + 3][lrB] = bv.w;
        __syncthreads();
#pragma unroll
        for (int kk = 0; kk < 16; kk++) {
            float a[2], b[4];
#pragma unroll
            for (int i = 0; i < 2; i++) a[i] = As[kk][ty * 2 + i];
#pragma unroll
            for (int j = 0; j < 4; j++) b[j] = Bs[kk][tx * 4 + j];
#pragma unroll
            for (int i = 0; i < 2; i++)
#pragma unroll
                for (int j = 0; j < 4; j++) acc[i][j] = fmaf(a[i], b[j], acc[i][j]);
        }
    }
    __syncthreads();
#pragma unroll
    for (int i = 0; i < 2; i++)
#pragma unroll
        for (int j = 0; j < 4; j++) Ss[ty * 2 + i][tx * 4 + j] = acc[i][j];
    __syncthreads();

    if (t < 32) {
        int tok = tok0 + t;
        float v1 = -1e30f, v2 = -1e30f;
        int i1 = 0, i2 = 0;
#pragma unroll 4
        for (int e = 0; e < N_EXP; e++) {
            float s = Ss[t][e];
            if (s > v1) { v2 = v1; i2 = i1; v1 = s; i1 = e; }
            else if (s > v2) { v2 = s; i2 = e; }
        }
        float ex = expf(v2 - v1);
        float wB = ex / (1.0f + ex);
        float wA = 1.0f - wB;

        int s1 = atomicAdd(&g_count[i1], 1);
        if (s1 < CAP) {
            g_row_tok[i1 * CAP + s1] = tok;
            g_pair_idx[tok * 2] = i1 * CAP + s1;
            g_pair_w[tok * 2] = wA;
        } else g_pair_idx[tok * 2] = -1;
        int s2 = atomicAdd(&g_count[i2], 1);
        if (s2 < CAP) {
            g_row_tok[i2 * CAP + s2] = tok;
            g_pair_idx[tok * 2 + 1] = i2 * CAP + s2;
            g_pair_w[tok * 2 + 1] = wB;
        } else g_pair_idx[tok * 2 + 1] = -1;
    }
}

// ---------------- GEMM core: fp16 1-term, A via cp.async, B fused fp32->fp16 --
// CTA 128x128, 256 threads, 8 warps of 64x32, BK=32, 3-stage smem ring.

#define LDGB(dst, src, s)                                     \
    {                                                         \
        const float4* _p = (const float4*)((src) + (s) * 32); \
        dst[0] = _p[0]; dst[1] = _p[1];                        \
        dst[2] = _p[2]; dst[3] = _p[3];                        \
    }
#define STSB(buf, sts, br)                                                        \
    {                                                                             \
        *(uint4*)((buf) + B_OFF + (sts)) =                                        \
            make_uint4(pack_h2(br[0].x, br[0].y), pack_h2(br[0].z, br[0].w),      \
                       pack_h2(br[1].x, br[1].y), pack_h2(br[1].z, br[1].w));     \
        *(uint4*)((buf) + B_OFF + (sts) + 16) =                                   \
            make_uint4(pack_h2(br[2].x, br[2].y), pack_h2(br[2].z, br[2].w),      \
                       pack_h2(br[3].x, br[3].y), pack_h2(br[3].z, br[3].w));     \
    }

// GEMM1: h = silu(xn[gather] @ w1[e]^T)
__global__ void __launch_bounds__(256, 2) k_gemm1(const float* __restrict__ w1) {
    int e = blockIdx.z;
    int cnt = min(g_count[e], CAP);
    int m0 = blockIdx.y * 128;
    if (m0 >= cnt) return;
    int n0 = blockIdx.x * 128;

    extern __shared__ char sm[];
    __shared__ int stok[128];
    int t = threadIdx.x, lane = t & 31, w = t >> 5;
    if (t < 128) {
        int s = m0 + t;
        stok[t] = (s < cnt) ? g_row_tok[e * CAP + s] : -1;
    }
    __syncthreads();

    int row = t >> 1;
    int half = t & 1;
    int atok = stok[row];
    uint32_t asz = (atok >= 0) ? 16u : 0u;
    const __half* a_src = g_xnh + ((atok >= 0) ? (size_t)atok * H_DIM : 0) + half * 16;
    const float* b_src = w1 + ((size_t)e * D_FF + n0 + row) * H_DIM + half * 16;
    uint32_t smb = smem_u32(sm);
    uint32_t sts = row * RB + half * 32;

    int wm = (w & 1) * 64;
    int wn = (w >> 1) * 32;
    uint32_t lm = (lane & 15) * RB + ((lane >> 4) << 4);
    uint32_t aoff = A_OFF + wm * RB + lm;
    uint32_t boff = B_OFF + wn * RB + lm;

    const int NC = H_DIM / 32;  // 32

    float4 br[4];
    LDGB(br, b_src, 0);
    STSB(sm, sts, br);
    LDGB(br, b_src, 1);
#pragma unroll
    for (int s = 0; s < 2; s++) {
        uint32_t d = smb + s * STAGE + sts;
        cp16(d + A_OFF, a_src + s * 32, asz);
        cp16(d + A_OFF + 16, a_src + s * 32 + 8, asz);
        CP_COMMIT();
    }

    float acc[4][4][4];
#pragma unroll
    for (int mf = 0; mf < 4; mf++)
#pragma unroll
        for (int nf = 0; nf < 4; nf++)
#pragma unroll
            for (int k = 0; k < 4; k++) acc[mf][nf][k] = 0.0f;

    // rotating stage pointers (modulo-free)
    uint32_t rd = smb;                        // compute stage (c)
    char*    w1s = sm + STAGE;                // STSB stage (c+1)
    uint32_t w2s = smb + 2 * STAGE;           // cp.async stage (c+2)
    const uint32_t smt = smb + 3 * STAGE;
    char* const smt_p = sm + 3 * STAGE;

#pragma unroll 1
    for (int c = 0; c < NC; c++) {
        CP_WAIT1();
        __syncthreads();
        if (c + 1 < NC) STSB(w1s, sts, br);
        if (c + 2 < NC) {
            LDGB(br, b_src, c + 2);
            uint32_t d = w2s + sts;
            cp16(d + A_OFF, a_src + (c + 2) * 32, asz);
            cp16(d + A_OFF + 16, a_src + (c + 2) * 32 + 8, asz);
        }
        CP_COMMIT();
#pragma unroll
        for (int kk = 0; kk < 2; kk++) {
            uint32_t ko = kk * 32;
            uint32_t ah[4][4], bh[2][4];
#pragma unroll
            for (int mf = 0; mf < 4; mf++) ldsm4(ah[mf], rd + aoff + mf * (16 * RB) + ko);
#pragma unroll
            for (int g = 0; g < 2; g++) ldsm4(bh[g], rd + boff + g * (16 * RB) + ko);
#pragma unroll
            for (int mf = 0; mf < 4; mf++)
#pragma unroll
                for (int nf = 0; nf < 4; nf++)
                    mma_f16(acc[mf][nf], ah[mf], bh[nf >> 1][nf & 1], bh[nf >> 1][(nf & 1) + 2]);
        }
        rd += STAGE;  if (rd == smt) rd = smb;
        w1s += STAGE; if (w1s == smt_p) w1s = sm;
        w2s += STAGE; if (w2s == smt) w2s = smb;
    }

    int rbase = m0 + wm + (lane >> 2);
    size_t eb = (size_t)e * CAP;
#pragma unroll
    for (int mf = 0; mf < 4; mf++) {
#pragma unroll
        for (int nf = 0; nf < 4; nf++) {
            int col = n0 + wn + nf * 8 + (lane & 3) * 2;
#pragma unroll
            for (int hh = 0; hh < 2; hh++) {
                size_t r = eb + rbase + mf * 16 + hh * 8;
                float s0 = silu_f(acc[mf][nf][hh * 2]);
                float s1 = silu_f(acc[mf][nf][hh * 2 + 1]);
                *(uint32_t*)(g_hh + r * D_FF + col) = pack_h2(s0, s1);
            }
        }
    }
}

// GEMM2: od = h @ w2[e]^T
__global__ void __launch_bounds__(256, 2) k_gemm2(const float* __restrict__ w2) {
    int e = blockIdx.z;
    int cnt = min(g_count[e], CAP);
    int m0 = blockIdx.y * 128;
    if (m0 >= cnt) return;
    int n0 = blockIdx.x * 128;

    extern __shared__ char sm[];
    int t = threadIdx.x, lane = t & 31, w = t >> 5;

    int row = t >> 1;
    int half = t & 1;
    const __half* a_src = g_hh + ((size_t)e * CAP + m0 + row) * D_FF + half * 16;
    const float* b_src = w2 + ((size_t)e * H_DIM + n0 + row) * D_FF + half * 16;
    uint32_t smb = smem_u32(sm);
    uint32_t sts = row * RB + half * 32;

    int wm = (w & 1) * 64;
    int wn = (w >> 1) * 32;
    uint32_t lm = (lane & 15) * RB + ((lane >> 4) << 4);
    uint32_t aoff = A_OFF + wm * RB + lm;
    uint32_t boff = B_OFF + wn * RB + lm;

    const int NC = D_FF / 32;  // 64

    float4 br[4];
    LDGB(br, b_src, 0);
    STSB(sm, sts, br);
    LDGB(br, b_src, 1);
#pragma unroll
    for (int s = 0; s < 2; s++) {
        uint32_t d = smb + s * STAGE + sts;
        cp16(d + A_OFF, a_src + s * 32, 16);
        cp16(d + A_OFF + 16, a_src + s * 32 + 8, 16);
        CP_COMMIT();
    }

    float acc[4][4][4];
#pragma unroll
    for (int mf = 0; mf < 4; mf++)
#pragma unroll
        for (int nf = 0; nf < 4; nf++)
#pragma unroll
            for (int k = 0; k < 4; k++) acc[mf][nf][k] = 0.0f;

    uint32_t rd = smb;
    char*    w1s = sm + STAGE;
    uint32_t w2s = smb + 2 * STAGE;
    const uint32_t smt = smb + 3 * STAGE;
    char* const smt_p = sm + 3 * STAGE;

#pragma unroll 1
    for (int c = 0; c < NC; c++) {
        CP_WAIT1();
        __syncthreads();
        if (c + 1 < NC) STSB(w1s, sts, br);
        if (c + 2 < NC) {
            LDGB(br, b_src, c + 2);
            uint32_t d = w2s + sts;
            cp16(d + A_OFF, a_src + (c + 2) * 32, 16);
            cp16(d + A_OFF + 16, a_src + (c + 2) * 32 + 8, 16);
        }
        CP_COMMIT();
#pragma unroll
        for (int kk = 0; kk < 2; kk++) {
            uint32_t ko = kk * 32;
            uint32_t ah[4][4], bh[2][4];
#pragma unroll
            for (int mf = 0; mf < 4; mf++) ldsm4(ah[mf], rd + aoff + mf * (16 * RB) + ko);
#pragma unroll
            for (int g = 0; g < 2; g++) ldsm4(bh[g], rd + boff + g * (16 * RB) + ko);
#pragma unroll
            for (int mf = 0; mf < 4; mf++)
#pragma unroll
                for (int nf = 0; nf < 4; nf++)
                    mma_f16(acc[mf][nf], ah[mf], bh[nf >> 1][nf & 1], bh[nf >> 1][(nf & 1) + 2]);
        }
        rd += STAGE;  if (rd == smt) rd = smb;
        w1s += STAGE; if (w1s == smt_p) w1s = sm;
        w2s += STAGE; if (w2s == smt) w2s = smb;
    }

    int rbase = m0 + wm + (lane >> 2);
    size_t eb = (size_t)e * CAP;
#pragma unroll
    for (int mf = 0; mf < 4; mf++) {
#pragma unroll
        for (int nf = 0; nf < 4; nf++) {
            int col = n0 + wn + nf * 8 + (lane & 3) * 2;
#pragma unroll
            for (int hh = 0; hh < 2; hh++) {
                size_t r = eb + rbase + mf * 16 + hh * 8;
                *(float2*)(g_od + r * H_DIM + col) =
                    make_float2(acc[mf][nf][hh * 2], acc[mf][nf][hh * 2 + 1]);
            }
        }
    }
}

// ---------------- 5: combine ---------------------------------------------------
__global__ void k_combine(const float* __restrict__ x, float* __restrict__ out) {
    int tok = blockIdx.x;
    int t = threadIdx.x;
    int p0 = g_pair_idx[tok * 2];
    int p1 = g_pair_idx[tok * 2 + 1];
    float w0 = g_pair_w[tok * 2];
    float w1 = g_pair_w[tok * 2 + 1];
    float4 v = ((const float4*)(x + (size_t)tok * H_DIM))[t];
    if (p0 >= 0) {
        float4 o = ((const float4*)(g_od + (size_t)p0 * H_DIM))[t];
        v.x += w0 * o.x; v.y += w0 * o.y; v.z += w0 * o.z; v.w += w0 * o.w;
    }
    if (p1 >= 0) {
        float4 o = ((const float4*)(g_od + (size_t)p1 * H_DIM))[t];
        v.x += w1 * o.x; v.y += w1 * o.y; v.z += w1 * o.z; v.w += w1 * o.w;
    }
    ((float4*)(out + (size_t)tok * H_DIM))[t] = v;
}

// ---------------- launch --------------------------------------------------------
extern "C" void kernel_launch(void* const* d_in, const int* in_sizes, int n_in,
                              void* d_out, int out_size) {
    const float* x        = (const float*)d_in[0];
    const float* rms_w    = (const float*)d_in[1];
    const float* router_w = (const float*)d_in[2];
    const float* w1       = (const float*)d_in[3];
    const float* w2       = (const float*)d_in[4];
    float* out = (float*)d_out;

    static bool attr_done = false;
    if (!attr_done) {
        cudaFuncSetAttribute(k_gemm1, cudaFuncAttributeMaxDynamicSharedMemorySize, SMEM_SZ);
        cudaFuncSetAttribute(k_gemm2, cudaFuncAttributeMaxDynamicSharedMemorySize, SMEM_SZ);
        attr_done = true;
    }

    k_zero_counts<<<1, 64>>>();
    k_rmsnorm<<<S_TOK, 256>>>(x, rms_w);
    k_router<<<S_TOK / 32, 256>>>(router_w);
    k_gemm1<<<dim3(D_FF / 128, CAP / 128, N_EXP), 256, SMEM_SZ>>>(w1);
    k_gemm2<<<dim3(H_DIM / 128, CAP / 128, N_EXP), 256, SMEM_SZ>>>(w2);
    k_combine<<<S_TOK, 256>>>(x, out);
}